// round 5
// baseline (speedup 1.0000x reference)
#include <cuda_runtime.h>
#include <cuda_fp16.h>
#include <math.h>

#define BATCH 4
#define CHN 64
#define HW 65536        // 256*256
#define NDS 4096        // 64*64 downsampled pixels
#define THITA_F 1.0e-4f
#define OUT2OFF (BATCH * CHN * HW)

// ---------------- scratch (device globals) ----------------------------------
__device__ float  g_xds[BATCH * CHN * NDS];     // down4(x) fp32 [b][c][n]
__device__ float  g_efd[BATCH * CHN * NDS];     // ef downsampled fp32 [b][c][n]
__device__ __half g_qh[BATCH * NDS * CHN];      // [b][n][d] f16
__device__ __half g_kh[BATCH * NDS * CHN];
__device__ __half g_vh[BATCH * NDS * CHN];
__device__ float  g_O[BATCH * CHN * NDS];       // final attention output [b][d][m]
__device__ float  g_Op[2 * BATCH * CHN * NDS];  // split-KV partial O (unnormalized)
__device__ float  g_ml[2 * BATCH * 2 * NDS];    // split-KV per-row m and l

// ============================================================================
// shared small-GEMM helpers (64x64 conv at ds pixels, 4 threads/pixel)
// ============================================================================
__device__ __forceinline__ void gemm64(float* acc, const float* ws,
                                       const float* src, int q, int nn)
{
    #pragma unroll
    for (int c = 0; c < 64; c += 4) {
        float v0 = src[c * 68 + nn],       v1 = src[(c + 1) * 68 + nn];
        float v2 = src[(c + 2) * 68 + nn], v3 = src[(c + 3) * 68 + nn];
        #pragma unroll
        for (int j = 0; j < 16; j++) {
            const float4 w4 = *(const float4*)&ws[(q * 16 + j) * 68 + c];
            acc[j] = fmaf(w4.x, v0, acc[j]);
            acc[j] = fmaf(w4.y, v1, acc[j]);
            acc[j] = fmaf(w4.z, v2, acc[j]);
            acc[j] = fmaf(w4.w, v3, acc[j]);
        }
    }
}
__device__ __forceinline__ void load_ws64(float* ws, const float* w, int t) {
    #pragma unroll
    for (int r = 0; r < 16; r++) {
        int i = r * 256 + t, o = i >> 6, c = i & 63;
        ws[o * 68 + c] = w[i];
    }
}

// ============================================================================
// K1: conv0_ds — x at downsampled pixels only (fp32). 256 thr, 64 px/block.
// ============================================================================
#define C0DS_SMEM (64 * 196 * 4 + 192 * 68 * 4)
__global__ __launch_bounds__(256) void conv0ds_kernel(
    const float* __restrict__ x1, const float* __restrict__ x2,
    const float* __restrict__ w,  const float* __restrict__ bias)
{
    extern __shared__ float sm[];
    float* ws = sm;                 // [64][196]
    float* as = sm + 64 * 196;      // [192][68]
    int t = threadIdx.x, q = t >> 6, nn = t & 63;
    int blk = blockIdx.x, b = blockIdx.y;
    int n = (blk << 6) + nn;

    for (int i = t; i < 12288; i += 256) {
        int o = i / 192, c = i - o * 192;
        ws[o * 196 + c] = w[i];
    }
    for (int i = t; i < 12288; i += 256) {
        int c = i >> 6, x = i & 63;
        const float* s = (c < 128) ? x1 + (size_t)(b * 128 + c) * HW
                                   : x2 + (size_t)(b * 64 + c - 128) * HW;
        as[c * 68 + x] = s[(blk << 10) + (x << 2)];
    }
    __syncthreads();

    float acc[16];
    #pragma unroll
    for (int j = 0; j < 16; j++) acc[j] = 0.0f;
    #pragma unroll
    for (int c = 0; c < 192; c += 4) {
        float v0 = as[c * 68 + nn],       v1 = as[(c + 1) * 68 + nn];
        float v2 = as[(c + 2) * 68 + nn], v3 = as[(c + 3) * 68 + nn];
        #pragma unroll
        for (int j = 0; j < 16; j++) {
            const float4 w4 = *(const float4*)&ws[(q * 16 + j) * 196 + c];
            acc[j] = fmaf(w4.x, v0, acc[j]);
            acc[j] = fmaf(w4.y, v1, acc[j]);
            acc[j] = fmaf(w4.z, v2, acc[j]);
            acc[j] = fmaf(w4.w, v3, acc[j]);
        }
    }
    #pragma unroll
    for (int j = 0; j < 16; j++) {
        int o = q * 16 + j;
        g_xds[(size_t)(b * 64 + o) * NDS + n] =
            fmaxf(acc[j] + __ldg(&bias[o]), 0.0f);
    }
}

// ============================================================================
// K2: ef path at ds pixels (fp32): two chained 64x64 convs.
// ============================================================================
#define EF_SMEM (3 * 64 * 68 * 4)
__global__ __launch_bounds__(256) void ef_kernel(
    const float* __restrict__ event,
    const float* __restrict__ w0, const float* __restrict__ b0,
    const float* __restrict__ w1, const float* __restrict__ b1)
{
    extern __shared__ float sm[];
    float* ws = sm;
    float* ts = sm + 64 * 68;
    float* ae = sm + 2 * 64 * 68;
    int t = threadIdx.x, q = t >> 6, nn = t & 63;
    int blk = blockIdx.x, b = blockIdx.y;
    int n = (blk << 6) + nn;

    load_ws64(ws, w0, t);
    for (int i = t; i < 4096; i += 256) {
        int c = i >> 6, x = i & 63;
        ae[c * 68 + x] = event[(size_t)(b * 64 + c) * HW + (blk << 10) + (x << 2)];
    }
    __syncthreads();

    float acc[16];
    #pragma unroll
    for (int j = 0; j < 16; j++) acc[j] = 0.0f;
    gemm64(acc, ws, ae, q, nn);
    #pragma unroll
    for (int j = 0; j < 16; j++)
        ts[(q * 16 + j) * 68 + nn] = fmaxf(acc[j] + __ldg(&b0[q * 16 + j]), 0.0f);
    __syncthreads();
    load_ws64(ws, w1, t);
    __syncthreads();

    #pragma unroll
    for (int j = 0; j < 16; j++) acc[j] = 0.0f;
    gemm64(acc, ws, ts, q, nn);
    #pragma unroll
    for (int j = 0; j < 16; j++) {
        int o = q * 16 + j;
        g_efd[(size_t)(b * 64 + o) * NDS + n] =
            fmaxf(acc[j] + __ldg(&b1[o]), 0.0f);
    }
}

// ============================================================================
// K3: qkv — t = relu(xw1@x_ds), q/v from t, k from ef_d. f16 [b][n][d] out.
// ============================================================================
#define QKV_SMEM (3 * 64 * 68 * 4)
__device__ __forceinline__ unsigned hpack(__half a, __half b) {
    __half2 h = __halves2half2(a, b);
    return *(unsigned*)&h;
}
__device__ __forceinline__ void store16h(__half* dst, const float* acc,
                                         const float* bias, int o0)
{
    unsigned u[8];
    #pragma unroll
    for (int j = 0; j < 8; j++) {
        float r0 = fmaxf(acc[2*j]   + __ldg(&bias[o0 + 2*j]),   0.0f);
        float r1 = fmaxf(acc[2*j+1] + __ldg(&bias[o0 + 2*j+1]), 0.0f);
        u[j] = hpack(__float2half_rn(r0), __float2half_rn(r1));
    }
    ((uint4*)dst)[0] = make_uint4(u[0], u[1], u[2], u[3]);
    ((uint4*)dst)[1] = make_uint4(u[4], u[5], u[6], u[7]);
}

__global__ __launch_bounds__(256) void qkv_kernel(
    const float* __restrict__ xw1, const float* __restrict__ xb1,
    const float* __restrict__ qw,  const float* __restrict__ qb,
    const float* __restrict__ kw,  const float* __restrict__ kb,
    const float* __restrict__ vw,  const float* __restrict__ vb)
{
    extern __shared__ float sm[];
    float* ws = sm;
    float* ts = sm + 64 * 68;
    float* as = sm + 2 * 64 * 68;
    int t = threadIdx.x, q = t >> 6, nn = t & 63;
    int blk = blockIdx.x, b = blockIdx.y;
    int n = (blk << 6) + nn;
    int o0 = q * 16;

    load_ws64(ws, xw1, t);
    for (int i = t; i < 4096; i += 256) {
        int c = i >> 6, x = i & 63;
        as[c * 68 + x] = g_xds[(size_t)(b * 64 + c) * NDS + (blk << 6) + x];
    }
    __syncthreads();

    float acc[16];
    #pragma unroll
    for (int j = 0; j < 16; j++) acc[j] = 0.0f;
    gemm64(acc, ws, as, q, nn);
    #pragma unroll
    for (int j = 0; j < 16; j++)
        ts[(o0 + j) * 68 + nn] = fmaxf(acc[j] + __ldg(&xb1[o0 + j]), 0.0f);
    __syncthreads();
    load_ws64(ws, qw, t);
    __syncthreads();

    #pragma unroll
    for (int j = 0; j < 16; j++) acc[j] = 0.0f;
    gemm64(acc, ws, ts, q, nn);
    store16h(g_qh + ((size_t)b * NDS + n) * 64 + o0, acc, qb, o0);
    __syncthreads();
    load_ws64(ws, vw, t);
    __syncthreads();

    #pragma unroll
    for (int j = 0; j < 16; j++) acc[j] = 0.0f;
    gemm64(acc, ws, ts, q, nn);
    store16h(g_vh + ((size_t)b * NDS + n) * 64 + o0, acc, vb, o0);
    __syncthreads();
    load_ws64(ws, kw, t);
    for (int i = t; i < 4096; i += 256) {
        int c = i >> 6, x = i & 63;
        as[c * 68 + x] = g_efd[(size_t)(b * 64 + c) * NDS + (blk << 6) + x];
    }
    __syncthreads();

    #pragma unroll
    for (int j = 0; j < 16; j++) acc[j] = 0.0f;
    gemm64(acc, ws, as, q, nn);
    store16h(g_kh + ((size_t)b * NDS + n) * 64 + o0, acc, kb, o0);
}

// ============================================================================
// K4: flash attention, f16 mma, SPLIT-KV (2 halves). 128 thr, M-tile 64.
// blockIdx.z = split; each CTA does 32 n-tiles, writes unnormalized O + (m,l).
// ============================================================================
#define SM_STRIDE 72
#define ATTN_SMEM ((64 * SM_STRIDE + 4 * 64 * SM_STRIDE) * 2)

__device__ __forceinline__ void mma16816(float* d,
    unsigned a0, unsigned a1, unsigned a2, unsigned a3,
    unsigned b0, unsigned b1)
{
    asm volatile(
        "mma.sync.aligned.m16n8k16.row.col.f32.f16.f16.f32 "
        "{%0,%1,%2,%3}, {%4,%5,%6,%7}, {%8,%9}, {%0,%1,%2,%3};\n"
        : "+f"(d[0]), "+f"(d[1]), "+f"(d[2]), "+f"(d[3])
        : "r"(a0), "r"(a1), "r"(a2), "r"(a3), "r"(b0), "r"(b1));
}
__device__ __forceinline__ void ldm4(unsigned* r, unsigned a) {
    asm volatile("ldmatrix.sync.aligned.m8n8.x4.shared.b16 {%0,%1,%2,%3}, [%4];\n"
        : "=r"(r[0]), "=r"(r[1]), "=r"(r[2]), "=r"(r[3]) : "r"(a));
}
__device__ __forceinline__ void ldm4t(unsigned* r, unsigned a) {
    asm volatile("ldmatrix.sync.aligned.m8n8.x4.trans.shared.b16 {%0,%1,%2,%3}, [%4];\n"
        : "=r"(r[0]), "=r"(r[1]), "=r"(r[2]), "=r"(r[3]) : "r"(a));
}
__device__ __forceinline__ void cpasync16(unsigned dst, const void* src) {
    asm volatile("cp.async.cg.shared.global [%0], [%1], 16;\n"
        :: "r"(dst), "l"(src));
}
__device__ __forceinline__ float sexp(float s, float c) {
    float t = fmaf(s, 12102203.16f, c);
    t = fmaxf(t, 0.0f);
    return __int_as_float(__float2int_rn(t));
}
__device__ __forceinline__ unsigned packh2(float a, float b) {
    __half2 h = __floats2half2_rn(a, b);
    return *(unsigned*)&h;
}

__global__ __launch_bounds__(128, 3) void attn_kernel()
{
    extern __shared__ __half smh[];
    __half* qs  = smh;                       // 64 x 72
    __half* ks0 = smh + 64 * SM_STRIDE;      // 2 x 64 x 72
    __half* vs0 = ks0 + 2 * 64 * SM_STRIDE;  // 2 x 64 x 72

    int tid  = threadIdx.x;
    int lane = tid & 31, w = tid >> 5;
    int gid  = lane >> 2, tig = lane & 3;
    int b    = blockIdx.y;
    int m0   = blockIdx.x << 6;
    int split = blockIdx.z;
    int it0  = split << 5;                   // 32 n-tiles per split

    const __half* qg = g_qh + (size_t)b * NDS * 64;
    const __half* kg = g_kh + (size_t)b * NDS * 64;
    const __half* vg = g_vh + (size_t)b * NDS * 64;

    unsigned qs_base = (unsigned)__cvta_generic_to_shared(qs);
    unsigned ks_base = (unsigned)__cvta_generic_to_shared(ks0);
    unsigned vs_base = (unsigned)__cvta_generic_to_shared(vs0);

    #pragma unroll
    for (int rep = 0; rep < 4; rep++) {
        int c = tid + rep * 128;
        int row = c >> 3, off = c & 7;
        cpasync16(ks_base + (row * SM_STRIDE + off * 8) * 2,
                  kg + (size_t)(it0 * 64 + row) * 64 + off * 8);
        cpasync16(vs_base + (row * SM_STRIDE + off * 8) * 2,
                  vg + (size_t)(it0 * 64 + row) * 64 + off * 8);
    }
    asm volatile("cp.async.commit_group;\n");

    for (int c = tid; c < 512; c += 128) {
        int row = c >> 3, off = c & 7;
        *(uint4*)(qs + row * SM_STRIDE + off * 8) =
            *(const uint4*)(qg + (size_t)(m0 + row) * 64 + off * 8);
    }
    asm volatile("cp.async.wait_group 0;\n");
    __syncthreads();

    unsigned qa[4][4];
    {
        int row = (w << 4) + (lane & 15);
        #pragma unroll
        for (int kc = 0; kc < 4; kc++) {
            int dof = kc * 16 + (lane >> 4) * 8;
            ldm4(qa[kc], qs_base + (row * SM_STRIDE + dof) * 2);
        }
    }

    float Of[8][4];
    #pragma unroll
    for (int dc = 0; dc < 8; dc++)
        #pragma unroll
        for (int q = 0; q < 4; q++) Of[dc][q] = 0.0f;
    float mrow0 = -1e30f, mrow1 = -1e30f, lrow0 = 0.0f, lrow1 = 0.0f;
    const unsigned ONES = 0x3C003C00u;

    for (int itr = 0; itr < 32; itr++) {
        int bf = itr & 1;
        unsigned ksb = ks_base + bf * 64 * SM_STRIDE * 2;
        unsigned vsb = vs_base + bf * 64 * SM_STRIDE * 2;

        if (itr + 1 < 32) {
            int n0n = (it0 + itr + 1) << 6;
            int nb  = (itr + 1) & 1;
            #pragma unroll
            for (int rep = 0; rep < 4; rep++) {
                int c = tid + rep * 128;
                int row = c >> 3, off = c & 7;
                cpasync16(ks_base + (nb * 64 * SM_STRIDE + row * SM_STRIDE + off * 8) * 2,
                          kg + (size_t)(n0n + row) * 64 + off * 8);
                cpasync16(vs_base + (nb * 64 * SM_STRIDE + row * SM_STRIDE + off * 8) * 2,
                          vg + (size_t)(n0n + row) * 64 + off * 8);
            }
            asm volatile("cp.async.commit_group;\n");
        }

        float S[8][4];
        #pragma unroll
        for (int nc = 0; nc < 8; nc++) {
            unsigned kb[8];
            int krow = nc * 8 + (lane & 7);
            int kd   = (lane >> 3) * 8;
            ldm4(kb,     ksb + (krow * SM_STRIDE + kd) * 2);
            ldm4(kb + 4, ksb + (krow * SM_STRIDE + 32 + kd) * 2);
            #pragma unroll
            for (int q = 0; q < 4; q++) S[nc][q] = 0.0f;
            mma16816(S[nc], qa[0][0], qa[0][1], qa[0][2], qa[0][3], kb[0], kb[1]);
            mma16816(S[nc], qa[1][0], qa[1][1], qa[1][2], qa[1][3], kb[2], kb[3]);
            mma16816(S[nc], qa[2][0], qa[2][1], qa[2][2], qa[2][3], kb[4], kb[5]);
            mma16816(S[nc], qa[3][0], qa[3][1], qa[3][2], qa[3][3], kb[6], kb[7]);
        }

        float tm0 = fmaxf(S[0][0], S[0][1]);
        float tm1 = fmaxf(S[0][2], S[0][3]);
        #pragma unroll
        for (int nc = 1; nc < 8; nc++) {
            tm0 = fmaxf(tm0, fmaxf(S[nc][0], S[nc][1]));
            tm1 = fmaxf(tm1, fmaxf(S[nc][2], S[nc][3]));
        }
        tm0 = fmaxf(tm0, __shfl_xor_sync(0xffffffffu, tm0, 1));
        tm0 = fmaxf(tm0, __shfl_xor_sync(0xffffffffu, tm0, 2));
        tm1 = fmaxf(tm1, __shfl_xor_sync(0xffffffffu, tm1, 1));
        tm1 = fmaxf(tm1, __shfl_xor_sync(0xffffffffu, tm1, 2));
        float nm0 = fmaxf(mrow0, tm0), nm1 = fmaxf(mrow1, tm1);
        float sc0 = exp2f((mrow0 - nm0) * 1.44269504f);
        float sc1 = exp2f((mrow1 - nm1) * 1.44269504f);
        mrow0 = nm0; mrow1 = nm1;
        float c0 = 1064866805.0f - nm0 * 12102203.16f;
        float c1 = 1064866805.0f - nm1 * 12102203.16f;

        unsigned P[4][4];
        #pragma unroll
        for (int jc = 0; jc < 4; jc++) {
            P[jc][0] = packh2(sexp(S[2*jc][0],   c0), sexp(S[2*jc][1],   c0));
            P[jc][1] = packh2(sexp(S[2*jc][2],   c1), sexp(S[2*jc][3],   c1));
            P[jc][2] = packh2(sexp(S[2*jc+1][0], c0), sexp(S[2*jc+1][1], c0));
            P[jc][3] = packh2(sexp(S[2*jc+1][2], c1), sexp(S[2*jc+1][3], c1));
        }

        float lf[4] = {0.0f, 0.0f, 0.0f, 0.0f};
        #pragma unroll
        for (int jc = 0; jc < 4; jc++)
            mma16816(lf, P[jc][0], P[jc][1], P[jc][2], P[jc][3], ONES, ONES);
        lrow0 = lrow0 * sc0 + lf[0];
        lrow1 = lrow1 * sc1 + lf[2];

        #pragma unroll
        for (int dc = 0; dc < 8; dc++) {
            Of[dc][0] *= sc0; Of[dc][1] *= sc0;
            Of[dc][2] *= sc1; Of[dc][3] *= sc1;
        }

        #pragma unroll
        for (int jc = 0; jc < 4; jc++) {
            int vrow = jc * 16 + (lane & 15);
            int vcb  = (lane >> 4) * 8;
            #pragma unroll
            for (int dcp = 0; dcp < 4; dcp++) {
                unsigned vb[4];
                ldm4t(vb, vsb + (vrow * SM_STRIDE + dcp * 16 + vcb) * 2);
                mma16816(Of[2*dcp],     P[jc][0], P[jc][1], P[jc][2], P[jc][3], vb[0], vb[1]);
                mma16816(Of[2*dcp + 1], P[jc][0], P[jc][1], P[jc][2], P[jc][3], vb[2], vb[3]);
            }
        }

        if (itr + 1 < 32) {
            asm volatile("cp.async.wait_group 0;\n");
            __syncthreads();
        }
    }

    // write UNNORMALIZED partial O and per-row (m, l)
    float* Op = g_Op + (size_t)split * BATCH * CHN * NDS;
    int m = m0 + (w << 4) + gid;
    #pragma unroll
    for (int dc = 0; dc < 8; dc++) {
        int d0 = dc * 8 + tig * 2;
        Op[(b * 64 + d0)     * NDS + m]     = Of[dc][0];
        Op[(b * 64 + d0 + 1) * NDS + m]     = Of[dc][1];
        Op[(b * 64 + d0)     * NDS + m + 8] = Of[dc][2];
        Op[(b * 64 + d0 + 1) * NDS + m + 8] = Of[dc][3];
    }
    if (tig == 0) {
        float* ml = g_ml + (size_t)((split * BATCH + b) * 2) * NDS;
        ml[m]           = mrow0;
        ml[m + 8]       = mrow1;
        ml[NDS + m]     = lrow0;
        ml[NDS + m + 8] = lrow1;
    }
}

// ============================================================================
// K4b: combine the two split-KV halves into g_O (normalized).
// ============================================================================
__global__ __launch_bounds__(128) void combine_kernel()
{
    int m = (blockIdx.x << 7) + threadIdx.x;
    int b = blockIdx.y;
    const float* ml0 = g_ml + (size_t)((0 * BATCH + b) * 2) * NDS;
    const float* ml1 = g_ml + (size_t)((1 * BATCH + b) * 2) * NDS;
    float m0 = ml0[m], l0 = ml0[NDS + m];
    float m1 = ml1[m], l1 = ml1[NDS + m];
    float M  = fmaxf(m0, m1);
    float s0 = exp2f((m0 - M) * 1.44269504f);
    float s1 = exp2f((m1 - M) * 1.44269504f);
    float inv = 1.0f / (l0 * s0 + l1 * s1);
    s0 *= inv; s1 *= inv;

    const float* Op0 = g_Op + (size_t)b * CHN * NDS + m;
    const float* Op1 = g_Op + (size_t)(BATCH + b) * CHN * NDS + m;
    float* Oo = g_O + (size_t)b * CHN * NDS + m;
    #pragma unroll 8
    for (int d = 0; d < 64; d++)
        Oo[d * NDS] = Op0[d * NDS] * s0 + Op1[d * NDS] * s1;
}

// ============================================================================
// K5: convout — full-res conv0 on tensor cores (f16 hi/lo 3-pass) fused with
// out = relu(conv+bias) + tg*up4(O), plus ef_up = up4(ef_d).
// ============================================================================
#define CO_OFF_WH  0
#define CO_OFF_WL  25600
#define CO_OFF_ACT 51200
#define CO_ACT_BUF 16896
#define CONVOUT_SMEM (51200 + 2 * 17408)

__global__ __launch_bounds__(256, 2) void convout_kernel(
    const float* __restrict__ x1, const float* __restrict__ x2,
    const float* __restrict__ w,  const float* __restrict__ bias,
    const float* __restrict__ gamma, float* __restrict__ out)
{
    extern __shared__ char smc[];
    __half* WH = (__half*)(smc + CO_OFF_WH);
    __half* WL = (__half*)(smc + CO_OFF_WL);
    unsigned smu = (unsigned)__cvta_generic_to_shared(smc);

    int t = threadIdx.x;
    int lane = t & 31, wp = t >> 5;
    int ln15 = lane & 15, hb8 = (lane >> 4) * 8;
    int y = blockIdx.x, b = blockIdx.y;
    int p0 = y << 8;
    int ndbase = (y >> 2) << 6;

    for (int i = t; i < 12288; i += 256) {
        int o = i / 192, c = i - o * 192;
        float v = w[i];
        __half h = __float2half_rn(v);
        WH[o * 200 + c] = h;
        WL[o * 200 + c] = __float2half_rn(v - __half2float(h));
    }

    int r = t >> 4, col0 = (t & 15) << 4;
    float f[16];
    {
        const float* s = x1 + (size_t)(b * 128 + r) * HW + p0 + col0;
        #pragma unroll
        for (int j = 0; j < 4; j++) *(float4*)&f[4*j] = *(const float4*)(s + 4*j);
        unsigned H[8], L[8];
        #pragma unroll
        for (int j = 0; j < 8; j++) {
            __half h0 = __float2half_rn(f[2*j]), h1 = __float2half_rn(f[2*j+1]);
            H[j] = hpack(h0, h1);
            L[j] = hpack(__float2half_rn(f[2*j]   - __half2float(h0)),
                         __float2half_rn(f[2*j+1] - __half2float(h1)));
        }
        __half* AH = (__half*)(smc + CO_OFF_ACT);
        __half* AL = AH + 4224;
        *(uint4*)&AH[r * 264 + col0]     = make_uint4(H[0], H[1], H[2], H[3]);
        *(uint4*)&AH[r * 264 + col0 + 8] = make_uint4(H[4], H[5], H[6], H[7]);
        *(uint4*)&AL[r * 264 + col0]     = make_uint4(L[0], L[1], L[2], L[3]);
        *(uint4*)&AL[r * 264 + col0 + 8] = make_uint4(L[4], L[5], L[6], L[7]);
    }
    __syncthreads();

    float acc[4][4][4];
    #pragma unroll
    for (int mt = 0; mt < 4; mt++)
        #pragma unroll
        for (int nb = 0; nb < 4; nb++)
            #pragma unroll
            for (int q = 0; q < 4; q++) acc[mt][nb][q] = 0.0f;

    unsigned whB = smu + CO_OFF_WH + (ln15 * 200 + hb8) * 2;
    unsigned wlB = smu + CO_OFF_WL + (ln15 * 200 + hb8) * 2;

    #pragma unroll 1
    for (int ks = 0; ks < 12; ks++) {
        if (ks < 11) {
            int c = (ks + 1) * 16 + r;
            const float* s = (c < 128) ? x1 + (size_t)(b * 128 + c) * HW
                                       : x2 + (size_t)(b * 64 + c - 128) * HW;
            s += p0 + col0;
            #pragma unroll
            for (int j = 0; j < 4; j++) *(float4*)&f[4*j] = *(const float4*)(s + 4*j);
        }

        int bf = ks & 1;
        unsigned actH = smu + CO_OFF_ACT + bf * CO_ACT_BUF +
                        (ln15 * 264 + wp * 32 + hb8) * 2;
        unsigned actL = actH + 4224 * 2;

        unsigned A[4][4], Bh[8], Bl[8];
        ldm4t(Bh,     actH);
        ldm4t(Bh + 4, actH + 32);
        ldm4t(Bl,     actL);
        ldm4t(Bl + 4, actL + 32);
        #pragma unroll
        for (int mt = 0; mt < 4; mt++)
            ldm4(A[mt], whB + mt * 6400 + ks * 32);
        #pragma unroll
        for (int mt = 0; mt < 4; mt++) {
            mma16816(acc[mt][0], A[mt][0], A[mt][1], A[mt][2], A[mt][3], Bh[0], Bh[1]);
            mma16816(acc[mt][1], A[mt][0], A[mt][1], A[mt][2], A[mt][3], Bh[2], Bh[3]);
            mma16816(acc[mt][2], A[mt][0], A[mt][1], A[mt][2], A[mt][3], Bh[4], Bh[5]);
            mma16816(acc[mt][3], A[mt][0], A[mt][1], A[mt][2], A[mt][3], Bh[6], Bh[7]);
            mma16816(acc[mt][0], A[mt][0], A[mt][1], A[mt][2], A[mt][3], Bl[0], Bl[1]);
            mma16816(acc[mt][1], A[mt][0], A[mt][1], A[mt][2], A[mt][3], Bl[2], Bl[3]);
            mma16816(acc[mt][2], A[mt][0], A[mt][1], A[mt][2], A[mt][3], Bl[4], Bl[5]);
            mma16816(acc[mt][3], A[mt][0], A[mt][1], A[mt][2], A[mt][3], Bl[6], Bl[7]);
        }
        #pragma unroll
        for (int mt = 0; mt < 4; mt++)
            ldm4(A[mt], wlB + mt * 6400 + ks * 32);
        #pragma unroll
        for (int mt = 0; mt < 4; mt++) {
            mma16816(acc[mt][0], A[mt][0], A[mt][1], A[mt][2], A[mt][3], Bh[0], Bh[1]);
            mma16816(acc[mt][1], A[mt][0], A[mt][1], A[mt][2], A[mt][3], Bh[2], Bh[3]);
            mma16816(acc[mt][2], A[mt][0], A[mt][1], A[mt][2], A[mt][3], Bh[4], Bh[5]);
            mma16816(acc[mt][3], A[mt][0], A[mt][1], A[mt][2], A[mt][3], Bh[6], Bh[7]);
        }

        if (ks < 11) {
            unsigned H[8], L[8];
            #pragma unroll
            for (int j = 0; j < 8; j++) {
                __half h0 = __float2half_rn(f[2*j]), h1 = __float2half_rn(f[2*j+1]);
                H[j] = hpack(h0, h1);
                L[j] = hpack(__float2half_rn(f[2*j]   - __half2float(h0)),
                             __float2half_rn(f[2*j+1] - __half2float(h1)));
            }
            __half* AH = (__half*)(smc + CO_OFF_ACT + (bf ^ 1) * CO_ACT_BUF);
            __half* AL = AH + 4224;
            *(uint4*)&AH[r * 264 + col0]     = make_uint4(H[0], H[1], H[2], H[3]);
            *(uint4*)&AH[r * 264 + col0 + 8] = make_uint4(H[4], H[5], H[6], H[7]);
            *(uint4*)&AL[r * 264 + col0]     = make_uint4(L[0], L[1], L[2], L[3]);
            *(uint4*)&AL[r * 264 + col0 + 8] = make_uint4(L[4], L[5], L[6], L[7]);
            __syncthreads();
        }
    }

    float ov[16], ev[16];
    {
        int o = t >> 2, c0 = (t & 3) << 4;
        const float* po = g_O   + (size_t)(b * 64 + o) * NDS + ndbase + c0;
        const float* pe = g_efd + (size_t)(b * 64 + o) * NDS + ndbase + c0;
        #pragma unroll
        for (int j = 0; j < 4; j++) {
            *(float4*)&ov[4*j] = *(const float4*)(po + 4*j);
            *(float4*)&ev[4*j] = *(const float4*)(pe + 4*j);
        }
    }
    __syncthreads();

    float* OS = (float*)(smc + CO_OFF_ACT);
    float* ES = OS + 64 * 68;
    {
        int o = t >> 2, c0 = (t & 3) << 4;
        #pragma unroll
        for (int j = 0; j < 4; j++) {
            *(float4*)&OS[o * 68 + c0 + 4*j] = *(const float4*)&ov[4*j];
            *(float4*)&ES[o * 68 + c0 + 4*j] = *(const float4*)&ev[4*j];
        }
    }
    __syncthreads();

    float tg = THITA_F * __ldg(gamma);
    int g = lane >> 2, tig = lane & 3;
    #pragma unroll
    for (int mt = 0; mt < 4; mt++) {
        int o = mt * 16 + g;
        float bb0 = __ldg(&bias[o]), bb1 = __ldg(&bias[o + 8]);
        #pragma unroll
        for (int nb = 0; nb < 4; nb++) {
            int px = wp * 32 + nb * 8 + tig * 2;
            int ndc = px >> 2;
            float a0 = tg * OS[o * 68 + ndc];
            float a1 = tg * OS[(o + 8) * 68 + ndc];
            float2 r0 = make_float2(fmaxf(acc[mt][nb][0] + bb0, 0.0f) + a0,
                                    fmaxf(acc[mt][nb][1] + bb0, 0.0f) + a0);
            float2 r1 = make_float2(fmaxf(acc[mt][nb][2] + bb1, 0.0f) + a1,
                                    fmaxf(acc[mt][nb][3] + bb1, 0.0f) + a1);
            *(float2*)(out + (size_t)(b * 64 + o)     * HW + p0 + px) = r0;
            *(float2*)(out + (size_t)(b * 64 + o + 8) * HW + p0 + px) = r1;
        }
    }

    int xq = t & 63;
    #pragma unroll
    for (int rep = 0; rep < 16; rep++) {
        int o = rep * 4 + (t >> 6);
        float v = ES[o * 68 + xq];
        *(float4*)(out + OUT2OFF + (size_t)(b * 64 + o) * HW + p0 + (xq << 2)) =
            make_float4(v, v, v, v);
    }
}

// ============================================================================
extern "C" void kernel_launch(void* const* d_in, const int* in_sizes, int n_in,
                              void* d_out, int out_size)
{
    const float* x1    = (const float*)d_in[0];
    const float* x2    = (const float*)d_in[1];
    const float* ev    = (const float*)d_in[2];
    const float* xw0   = (const float*)d_in[3];
    const float* xb0   = (const float*)d_in[4];
    const float* xw1   = (const float*)d_in[5];
    const float* xb1   = (const float*)d_in[6];
    const float* ew0   = (const float*)d_in[7];
    const float* eb0   = (const float*)d_in[8];
    const float* ew1   = (const float*)d_in[9];
    const float* eb1   = (const float*)d_in[10];
    const float* qw    = (const float*)d_in[11];
    const float* qb    = (const float*)d_in[12];
    const float* kw    = (const float*)d_in[13];
    const float* kb    = (const float*)d_in[14];
    const float* vw    = (const float*)d_in[15];
    const float* vb    = (const float*)d_in[16];
    const float* gamma = (const float*)d_in[17];
    float* out = (float*)d_out;

    cudaFuncSetAttribute(conv0ds_kernel,
                         cudaFuncAttributeMaxDynamicSharedMemorySize, C0DS_SMEM);
    cudaFuncSetAttribute(ef_kernel,
                         cudaFuncAttributeMaxDynamicSharedMemorySize, EF_SMEM);
    cudaFuncSetAttribute(qkv_kernel,
                         cudaFuncAttributeMaxDynamicSharedMemorySize, QKV_SMEM);
    cudaFuncSetAttribute(attn_kernel,
                         cudaFuncAttributeMaxDynamicSharedMemorySize, ATTN_SMEM);
    cudaFuncSetAttribute(convout_kernel,
                         cudaFuncAttributeMaxDynamicSharedMemorySize, CONVOUT_SMEM);

    conv0ds_kernel<<<dim3(NDS / 64, BATCH), 256, C0DS_SMEM>>>(x1, x2, xw0, xb0);
    ef_kernel<<<dim3(NDS / 64, BATCH), 256, EF_SMEM>>>(ev, ew0, eb0, ew1, eb1);
    qkv_kernel<<<dim3(NDS / 64, BATCH), 256, QKV_SMEM>>>(xw1, xb1, qw, qb, kw, kb, vw, vb);
    attn_kernel<<<dim3(NDS / 64, BATCH, 2), 128, ATTN_SMEM>>>();
    combine_kernel<<<dim3(NDS / 128, BATCH), 128>>>();
    convout_kernel<<<dim3(256, BATCH), 256, CONVOUT_SMEM>>>(x1, x2, xw0, xb0, gamma, out);
}

// round 6
// speedup vs baseline: 1.2269x; 1.2269x over previous
#include <cuda_runtime.h>
#include <cuda_fp16.h>
#include <math.h>

#define BATCH 4
#define CHN 64
#define HW 65536        // 256*256
#define NDS 4096        // 64*64 downsampled pixels
#define THITA_F 1.0e-4f
#define OUT2OFF (BATCH * CHN * HW)

// ---------------- scratch (device globals) ----------------------------------
__device__ __half g_xdsh[BATCH * CHN * NDS];    // down4(x) f16 [b][c][n]
__device__ float  g_efd [BATCH * CHN * NDS];    // ef ds fp32 [b][c][n] (feeds ef_up)
__device__ __half g_efdh[BATCH * CHN * NDS];    // ef ds f16 [b][c][n] (feeds k conv)
__device__ __half g_qh[BATCH * NDS * CHN];      // [b][n][d] f16
__device__ __half g_kh[BATCH * NDS * CHN];
__device__ __half g_vh[BATCH * NDS * CHN];
__device__ float  g_O[BATCH * CHN * NDS];       // attention output [b][d][m]

// ============================================================================
// mma / ldmatrix helpers
// ============================================================================
__device__ __forceinline__ void mma16816(float* d,
    unsigned a0, unsigned a1, unsigned a2, unsigned a3,
    unsigned b0, unsigned b1)
{
    asm volatile(
        "mma.sync.aligned.m16n8k16.row.col.f32.f16.f16.f32 "
        "{%0,%1,%2,%3}, {%4,%5,%6,%7}, {%8,%9}, {%0,%1,%2,%3};\n"
        : "+f"(d[0]), "+f"(d[1]), "+f"(d[2]), "+f"(d[3])
        : "r"(a0), "r"(a1), "r"(a2), "r"(a3), "r"(b0), "r"(b1));
}
__device__ __forceinline__ void ldm4(unsigned* r, unsigned a) {
    asm volatile("ldmatrix.sync.aligned.m8n8.x4.shared.b16 {%0,%1,%2,%3}, [%4];\n"
        : "=r"(r[0]), "=r"(r[1]), "=r"(r[2]), "=r"(r[3]) : "r"(a));
}
__device__ __forceinline__ void ldm4t(unsigned* r, unsigned a) {
    asm volatile("ldmatrix.sync.aligned.m8n8.x4.trans.shared.b16 {%0,%1,%2,%3}, [%4];\n"
        : "=r"(r[0]), "=r"(r[1]), "=r"(r[2]), "=r"(r[3]) : "r"(a));
}
__device__ __forceinline__ void cpasync16(unsigned dst, const void* src) {
    asm volatile("cp.async.cg.shared.global [%0], [%1], 16;\n"
        :: "r"(dst), "l"(src));
}
__device__ __forceinline__ unsigned hpack(__half a, __half b) {
    __half2 h = __halves2half2(a, b);
    return *(unsigned*)&h;
}
__device__ __forceinline__ unsigned packh2(float a, float b) {
    __half2 h = __floats2half2_rn(a, b);
    return *(unsigned*)&h;
}
__device__ __forceinline__ float sexp(float s, float c) {
    float t = fmaf(s, 12102203.16f, c);
    t = fmaxf(t, 0.0f);
    return __int_as_float(__float2int_rn(t));
}

// single-pass f16 GEMM: acc[8][4] += W(16 rows at wb) @ act(K=16*nks x 64, stride 72)
__device__ __forceinline__ void gemm1p(float acc[8][4], unsigned wb, int wstride,
                                       unsigned ab, int nks, int lane)
{
    int ln15 = lane & 15, hb8 = (lane >> 4) * 8;
    unsigned wl = wb + (ln15 * wstride + hb8) * 2;
    #pragma unroll
    for (int ks = 0; ks < nks; ks++) {
        unsigned al = ab + ((ks * 16 + ln15) * 72 + hb8) * 2;
        unsigned B[16], A[4];
        ldm4t(B,      al);
        ldm4t(B + 4,  al + 32);
        ldm4t(B + 8,  al + 64);
        ldm4t(B + 12, al + 96);
        ldm4(A, wl + ks * 32);
        #pragma unroll
        for (int nc = 0; nc < 8; nc++) {
            int ib = (nc >> 1) * 4 + (nc & 1) * 2;
            mma16816(acc[nc], A[0], A[1], A[2], A[3], B[ib], B[ib + 1]);
        }
    }
}

// 3-pass hi/lo GEMM (K=64): acc += Wh@Ah + Wh@Al + Wl@Ah
__device__ __forceinline__ void gemm3p(float acc[8][4],
    unsigned wh, unsigned wlo, unsigned ah, unsigned alo, int lane)
{
    int ln15 = lane & 15, hb8 = (lane >> 4) * 8;
    unsigned wbh = wh  + (ln15 * 72 + hb8) * 2;
    unsigned wbl = wlo + (ln15 * 72 + hb8) * 2;
    #pragma unroll
    for (int ks = 0; ks < 4; ks++) {
        unsigned abh = ah  + ((ks * 16 + ln15) * 72 + hb8) * 2;
        unsigned abl = alo + ((ks * 16 + ln15) * 72 + hb8) * 2;
        unsigned Bh[16], Bl[16], Wf[4], Lf[4];
        ldm4t(Bh,      abh);
        ldm4t(Bh + 4,  abh + 32);
        ldm4t(Bh + 8,  abh + 64);
        ldm4t(Bh + 12, abh + 96);
        ldm4t(Bl,      abl);
        ldm4t(Bl + 4,  abl + 32);
        ldm4t(Bl + 8,  abl + 64);
        ldm4t(Bl + 12, abl + 96);
        ldm4(Wf, wbh + ks * 32);
        ldm4(Lf, wbl + ks * 32);
        #pragma unroll
        for (int nc = 0; nc < 8; nc++) {
            int ib = (nc >> 1) * 4 + (nc & 1) * 2;
            mma16816(acc[nc], Wf[0], Wf[1], Wf[2], Wf[3], Bh[ib], Bh[ib + 1]);
            mma16816(acc[nc], Wf[0], Wf[1], Wf[2], Wf[3], Bl[ib], Bl[ib + 1]);
            mma16816(acc[nc], Lf[0], Lf[1], Lf[2], Lf[3], Bh[ib], Bh[ib + 1]);
        }
    }
}

// ============================================================================
// K1: prep — z=0: conv0_ds (f16 1-pass, 192->64) -> g_xdsh
//            z=1: ef chain (f16 hi/lo 3-pass, 64->64 twice) -> g_efd, g_efdh
// 128 thr (4 warps), 64 px/block, grid (64, BATCH, 2)
// ============================================================================
#define PREP_SMEM (64 * 200 * 2 + 192 * 72 * 2)   // 53248

__global__ __launch_bounds__(128) void prep_kernel(
    const float* __restrict__ x1, const float* __restrict__ x2,
    const float* __restrict__ ev,
    const float* __restrict__ xw0, const float* __restrict__ xb0,
    const float* __restrict__ ew0, const float* __restrict__ eb0,
    const float* __restrict__ ew1, const float* __restrict__ eb1)
{
    extern __shared__ char smc[];
    unsigned smu = (unsigned)__cvta_generic_to_shared(smc);
    int t = threadIdx.x, lane = t & 31, w = t >> 5;
    int gid = lane >> 2, tig = lane & 3;
    int blk = blockIdx.x, b = blockIdx.y;
    int n0 = blk << 6;

    float acc[8][4];
    #pragma unroll
    for (int nc = 0; nc < 8; nc++)
        #pragma unroll
        for (int q = 0; q < 4; q++) acc[nc][q] = 0.0f;

    if (blockIdx.z == 0) {
        // ---------------- conv0_ds ----------------
        __half* W  = (__half*)smc;                 // [64][200]
        __half* Ac = (__half*)(smc + 64 * 200 * 2);// [192][72]
        for (int i = t; i < 12288; i += 128) {
            int o = i / 192, c = i - o * 192;
            W[o * 200 + c] = __float2half_rn(xw0[i]);
        }
        for (int i = t; i < 12288; i += 128) {
            int c = i >> 6, x = i & 63;
            const float* s = (c < 128) ? x1 + (size_t)(b * 128 + c) * HW
                                       : x2 + (size_t)(b * 64 + c - 128) * HW;
            Ac[c * 72 + x] = __float2half_rn(s[(blk << 10) + (x << 2)]);
        }
        __syncthreads();

        gemm1p(acc, smu + (w * 16) * 200 * 2, 200,
               smu + 64 * 200 * 2, 12, lane);

        int o = (w << 4) + gid;
        float b0 = __ldg(&xb0[o]), b1 = __ldg(&xb0[o + 8]);
        #pragma unroll
        for (int nc = 0; nc < 8; nc++) {
            int n = n0 + nc * 8 + tig * 2;
            *(__half2*)&g_xdsh[(size_t)(b * 64 + o) * NDS + n] =
                __floats2half2_rn(fmaxf(acc[nc][0] + b0, 0.0f),
                                  fmaxf(acc[nc][1] + b0, 0.0f));
            *(__half2*)&g_xdsh[(size_t)(b * 64 + o + 8) * NDS + n] =
                __floats2half2_rn(fmaxf(acc[nc][2] + b1, 0.0f),
                                  fmaxf(acc[nc][3] + b1, 0.0f));
        }
    } else {
        // ---------------- ef chain ----------------
        __half* Wh = (__half*)smc;                     // [64][72]
        __half* Wl = Wh + 64 * 72;
        __half* Ah = Wl + 64 * 72;
        __half* Al = Ah + 64 * 72;
        unsigned oWh = smu, oWl = smu + 9216, oAh = smu + 18432, oAl = smu + 27648;

        for (int i = t; i < 4096; i += 128) {
            float v = ew0[i];
            __half h = __float2half_rn(v);
            int o = i >> 6, c = i & 63;
            Wh[o * 72 + c] = h;
            Wl[o * 72 + c] = __float2half_rn(v - __half2float(h));
        }
        for (int i = t; i < 4096; i += 128) {
            int c = i >> 6, x = i & 63;
            float v = ev[(size_t)(b * 64 + c) * HW + (blk << 10) + (x << 2)];
            __half h = __float2half_rn(v);
            Ah[c * 72 + x] = h;
            Al[c * 72 + x] = __float2half_rn(v - __half2float(h));
        }
        __syncthreads();

        gemm3p(acc, oWh + (w * 16) * 144, oWl + (w * 16) * 144, oAh, oAl, lane);
        __syncthreads();   // all reads of Ah/Al/W done

        // t -> Ah/Al (re-split), reload weights = ew1
        {
            int o = (w << 4) + gid;
            float b0 = __ldg(&eb0[o]), b1 = __ldg(&eb0[o + 8]);
            #pragma unroll
            for (int nc = 0; nc < 8; nc++) {
                int px = nc * 8 + tig * 2;
                float t0 = fmaxf(acc[nc][0] + b0, 0.0f);
                float t1 = fmaxf(acc[nc][1] + b0, 0.0f);
                float t2 = fmaxf(acc[nc][2] + b1, 0.0f);
                float t3 = fmaxf(acc[nc][3] + b1, 0.0f);
                __half h0 = __float2half_rn(t0), h1 = __float2half_rn(t1);
                __half h2 = __float2half_rn(t2), h3 = __float2half_rn(t3);
                *(__half2*)&Ah[o * 72 + px] = __halves2half2(h0, h1);
                *(__half2*)&Al[o * 72 + px] = __floats2half2_rn(
                    t0 - __half2float(h0), t1 - __half2float(h1));
                *(__half2*)&Ah[(o + 8) * 72 + px] = __halves2half2(h2, h3);
                *(__half2*)&Al[(o + 8) * 72 + px] = __floats2half2_rn(
                    t2 - __half2float(h2), t3 - __half2float(h3));
            }
        }
        for (int i = t; i < 4096; i += 128) {
            float v = ew1[i];
            __half h = __float2half_rn(v);
            int o = i >> 6, c = i & 63;
            Wh[o * 72 + c] = h;
            Wl[o * 72 + c] = __float2half_rn(v - __half2float(h));
        }
        __syncthreads();

        #pragma unroll
        for (int nc = 0; nc < 8; nc++)
            #pragma unroll
            for (int q = 0; q < 4; q++) acc[nc][q] = 0.0f;
        gemm3p(acc, oWh + (w * 16) * 144, oWl + (w * 16) * 144, oAh, oAl, lane);

        int o = (w << 4) + gid;
        float b0 = __ldg(&eb1[o]), b1 = __ldg(&eb1[o + 8]);
        #pragma unroll
        for (int nc = 0; nc < 8; nc++) {
            int n = n0 + nc * 8 + tig * 2;
            float r0 = fmaxf(acc[nc][0] + b0, 0.0f);
            float r1 = fmaxf(acc[nc][1] + b0, 0.0f);
            float r2 = fmaxf(acc[nc][2] + b1, 0.0f);
            float r3 = fmaxf(acc[nc][3] + b1, 0.0f);
            *(float2*)&g_efd[(size_t)(b * 64 + o) * NDS + n]     = make_float2(r0, r1);
            *(float2*)&g_efd[(size_t)(b * 64 + o + 8) * NDS + n] = make_float2(r2, r3);
            *(__half2*)&g_efdh[(size_t)(b * 64 + o) * NDS + n]     = __floats2half2_rn(r0, r1);
            *(__half2*)&g_efdh[(size_t)(b * 64 + o + 8) * NDS + n] = __floats2half2_rn(r2, r3);
        }
    }
}

// ============================================================================
// K2: qkv — all f16 1-pass mma. t = xw1@xds; q,v from t; k from efd.
// 128 thr, 64 px/block, grid (64, BATCH). Outputs [b][n][d] f16.
// ============================================================================
#define QKV_SMEM (4 * 64 * 72 * 2)   // 36864: W | Act | Tbuf | Trb

__global__ __launch_bounds__(128) void qkv_kernel(
    const float* __restrict__ xw1, const float* __restrict__ xb1,
    const float* __restrict__ qw,  const float* __restrict__ qb,
    const float* __restrict__ kw,  const float* __restrict__ kb,
    const float* __restrict__ vw,  const float* __restrict__ vb)
{
    extern __shared__ char smc[];
    unsigned smu = (unsigned)__cvta_generic_to_shared(smc);
    __half* W   = (__half*)smc;              // [64][72]
    __half* Act = W + 64 * 72;
    __half* Tb  = Act + 64 * 72;
    __half* Tr  = Tb + 64 * 72;
    unsigned oW = smu, oAct = smu + 9216, oTb = smu + 18432;

    int t = threadIdx.x, lane = t & 31, w = t >> 5;
    int gid = lane >> 2, tig = lane & 3;
    int blk = blockIdx.x, b = blockIdx.y;
    int n0 = blk << 6;
    int o = (w << 4) + gid;

    // load act tile (x_ds) and xw1
    for (int i = t; i < 512; i += 128) {
        int row = i >> 3, off = i & 7;
        *(uint4*)&Act[row * 72 + off * 8] =
            *(const uint4*)&g_xdsh[(size_t)(b * 64 + row) * NDS + n0 + off * 8];
    }
    for (int i = t; i < 4096; i += 128)
        W[(i >> 6) * 72 + (i & 63)] = __float2half_rn(xw1[i]);
    __syncthreads();

    float acc[8][4];
    // ---- t = relu(xw1 @ xds + xb1) -> Tb [c][px]
    #pragma unroll
    for (int nc = 0; nc < 8; nc++)
        #pragma unroll
        for (int q = 0; q < 4; q++) acc[nc][q] = 0.0f;
    gemm1p(acc, oW + (w * 16) * 144, 72, oAct, 4, lane);
    {
        float b0 = __ldg(&xb1[o]), b1 = __ldg(&xb1[o + 8]);
        #pragma unroll
        for (int nc = 0; nc < 8; nc++) {
            int px = nc * 8 + tig * 2;
            *(__half2*)&Tb[o * 72 + px] = __floats2half2_rn(
                fmaxf(acc[nc][0] + b0, 0.0f), fmaxf(acc[nc][1] + b0, 0.0f));
            *(__half2*)&Tb[(o + 8) * 72 + px] = __floats2half2_rn(
                fmaxf(acc[nc][2] + b1, 0.0f), fmaxf(acc[nc][3] + b1, 0.0f));
        }
    }
    __syncthreads();
    for (int i = t; i < 4096; i += 128)
        W[(i >> 6) * 72 + (i & 63)] = __float2half_rn(qw[i]);
    __syncthreads();

    // ---- q = relu(qw @ t) -> transpose -> g_qh
    #pragma unroll
    for (int nc = 0; nc < 8; nc++)
        #pragma unroll
        for (int q = 0; q < 4; q++) acc[nc][q] = 0.0f;
    gemm1p(acc, oW + (w * 16) * 144, 72, oTb, 4, lane);
    {
        float b0 = __ldg(&qb[o]), b1 = __ldg(&qb[o + 8]);
        #pragma unroll
        for (int nc = 0; nc < 8; nc++) {
            int px = nc * 8 + tig * 2;
            Tr[px * 72 + o]           = __float2half_rn(fmaxf(acc[nc][0] + b0, 0.0f));
            Tr[(px + 1) * 72 + o]     = __float2half_rn(fmaxf(acc[nc][1] + b0, 0.0f));
            Tr[px * 72 + o + 8]       = __float2half_rn(fmaxf(acc[nc][2] + b1, 0.0f));
            Tr[(px + 1) * 72 + o + 8] = __float2half_rn(fmaxf(acc[nc][3] + b1, 0.0f));
        }
    }
    __syncthreads();
    for (int i = t; i < 512; i += 128) {
        int row = i >> 3, off = i & 7;
        *(uint4*)&g_qh[((size_t)b * NDS + n0 + row) * 64 + off * 8] =
            *(uint4*)&Tr[row * 72 + off * 8];
    }
    for (int i = t; i < 4096; i += 128)
        W[(i >> 6) * 72 + (i & 63)] = __float2half_rn(vw[i]);
    __syncthreads();

    // ---- v = relu(vw @ t)
    #pragma unroll
    for (int nc = 0; nc < 8; nc++)
        #pragma unroll
        for (int q = 0; q < 4; q++) acc[nc][q] = 0.0f;
    gemm1p(acc, oW + (w * 16) * 144, 72, oTb, 4, lane);
    {
        float b0 = __ldg(&vb[o]), b1 = __ldg(&vb[o + 8]);
        #pragma unroll
        for (int nc = 0; nc < 8; nc++) {
            int px = nc * 8 + tig * 2;
            Tr[px * 72 + o]           = __float2half_rn(fmaxf(acc[nc][0] + b0, 0.0f));
            Tr[(px + 1) * 72 + o]     = __float2half_rn(fmaxf(acc[nc][1] + b0, 0.0f));
            Tr[px * 72 + o + 8]       = __float2half_rn(fmaxf(acc[nc][2] + b1, 0.0f));
            Tr[(px + 1) * 72 + o + 8] = __float2half_rn(fmaxf(acc[nc][3] + b1, 0.0f));
        }
    }
    __syncthreads();
    for (int i = t; i < 512; i += 128) {
        int row = i >> 3, off = i & 7;
        *(uint4*)&g_vh[((size_t)b * NDS + n0 + row) * 64 + off * 8] =
            *(uint4*)&Tr[row * 72 + off * 8];
    }
    // load kw and efd act
    for (int i = t; i < 4096; i += 128)
        W[(i >> 6) * 72 + (i & 63)] = __float2half_rn(kw[i]);
    for (int i = t; i < 512; i += 128) {
        int row = i >> 3, off = i & 7;
        *(uint4*)&Act[row * 72 + off * 8] =
            *(const uint4*)&g_efdh[(size_t)(b * 64 + row) * NDS + n0 + off * 8];
    }
    __syncthreads();

    // ---- k = relu(kw @ efd)
    #pragma unroll
    for (int nc = 0; nc < 8; nc++)
        #pragma unroll
        for (int q = 0; q < 4; q++) acc[nc][q] = 0.0f;
    gemm1p(acc, oW + (w * 16) * 144, 72, oAct, 4, lane);
    {
        float b0 = __ldg(&kb[o]), b1 = __ldg(&kb[o + 8]);
        #pragma unroll
        for (int nc = 0; nc < 8; nc++) {
            int px = nc * 8 + tig * 2;
            Tr[px * 72 + o]           = __float2half_rn(fmaxf(acc[nc][0] + b0, 0.0f));
            Tr[(px + 1) * 72 + o]     = __float2half_rn(fmaxf(acc[nc][1] + b0, 0.0f));
            Tr[px * 72 + o + 8]       = __float2half_rn(fmaxf(acc[nc][2] + b1, 0.0f));
            Tr[(px + 1) * 72 + o + 8] = __float2half_rn(fmaxf(acc[nc][3] + b1, 0.0f));
        }
    }
    __syncthreads();
    for (int i = t; i < 512; i += 128) {
        int row = i >> 3, off = i & 7;
        *(uint4*)&g_kh[((size_t)b * NDS + n0 + row) * 64 + off * 8] =
            *(uint4*)&Tr[row * 72 + off * 8];
    }
}

// ============================================================================
// K3: flash attention (round-3 best config: 256 thr, M-tile 128)
// ============================================================================
#define SM_STRIDE 72
#define ATTN_SMEM ((128 * SM_STRIDE + 4 * 64 * SM_STRIDE) * 2)

__global__ __launch_bounds__(256, 1) void attn_kernel()
{
    extern __shared__ __half smh[];
    __half* qs  = smh;
    __half* ks0 = smh + 128 * SM_STRIDE;
    __half* vs0 = ks0 + 2 * 64 * SM_STRIDE;

    int tid  = threadIdx.x;
    int lane = tid & 31, w = tid >> 5;
    int gid  = lane >> 2, tig = lane & 3;
    int b    = blockIdx.y;
    int m0   = blockIdx.x << 7;

    const __half* qg = g_qh + (size_t)b * NDS * 64;
    const __half* kg = g_kh + (size_t)b * NDS * 64;
    const __half* vg = g_vh + (size_t)b * NDS * 64;

    unsigned qs_base = (unsigned)__cvta_generic_to_shared(qs);
    unsigned ks_base = (unsigned)__cvta_generic_to_shared(ks0);
    unsigned vs_base = (unsigned)__cvta_generic_to_shared(vs0);

    #pragma unroll
    for (int rep = 0; rep < 2; rep++) {
        int c = tid + rep * 256;
        int row = c >> 3, off = c & 7;
        cpasync16(ks_base + (row * SM_STRIDE + off * 8) * 2, kg + row * 64 + off * 8);
        cpasync16(vs_base + (row * SM_STRIDE + off * 8) * 2, vg + row * 64 + off * 8);
    }
    asm volatile("cp.async.commit_group;\n");

    for (int c = tid; c < 1024; c += 256) {
        int row = c >> 3, off = c & 7;
        *(uint4*)(qs + row * SM_STRIDE + off * 8) =
            *(const uint4*)(qg + (size_t)(m0 + row) * 64 + off * 8);
    }
    asm volatile("cp.async.wait_group 0;\n");
    __syncthreads();

    unsigned qa[4][4];
    {
        int row = (w << 4) + (lane & 15);
        #pragma unroll
        for (int kc = 0; kc < 4; kc++) {
            int dof = kc * 16 + (lane >> 4) * 8;
            ldm4(qa[kc], qs_base + (row * SM_STRIDE + dof) * 2);
        }
    }

    float Of[8][4];
    #pragma unroll
    for (int dc = 0; dc < 8; dc++)
        #pragma unroll
        for (int q = 0; q < 4; q++) Of[dc][q] = 0.0f;
    float mrow0 = -1e30f, mrow1 = -1e30f, lrow0 = 0.0f, lrow1 = 0.0f;
    const unsigned ONES = 0x3C003C00u;

    for (int it = 0; it < 64; it++) {
        int bf = it & 1;
        unsigned ksb = ks_base + bf * 64 * SM_STRIDE * 2;
        unsigned vsb = vs_base + bf * 64 * SM_STRIDE * 2;

        if (it + 1 < 64) {
            int n0n = (it + 1) << 6;
            int nb  = (it + 1) & 1;
            #pragma unroll
            for (int rep = 0; rep < 2; rep++) {
                int c = tid + rep * 256;
                int row = c >> 3, off = c & 7;
                cpasync16(ks_base + (nb * 64 * SM_STRIDE + row * SM_STRIDE + off * 8) * 2,
                          kg + (size_t)(n0n + row) * 64 + off * 8);
                cpasync16(vs_base + (nb * 64 * SM_STRIDE + row * SM_STRIDE + off * 8) * 2,
                          vg + (size_t)(n0n + row) * 64 + off * 8);
            }
            asm volatile("cp.async.commit_group;\n");
        }

        float S[8][4];
        #pragma unroll
        for (int nc = 0; nc < 8; nc++) {
            unsigned kb[8];
            int krow = nc * 8 + (lane & 7);
            int kd   = (lane >> 3) * 8;
            ldm4(kb,     ksb + (krow * SM_STRIDE + kd) * 2);
            ldm4(kb + 4, ksb + (krow * SM_STRIDE + 32 + kd) * 2);
            #pragma unroll
            for (int q = 0; q < 4; q++) S[nc][q] = 0.0f;
            mma16816(S[nc], qa[0][0], qa[0][1], qa[0][2], qa[0][3], kb[0], kb[1]);
            mma16816(S[nc], qa[1][0], qa[1][1], qa[1][2], qa[1][3], kb[2], kb[3]);
            mma16816(S[nc], qa[2][0], qa[2][1], qa[2][2], qa[2][3], kb[4], kb[5]);
            mma16816(S[nc], qa[3][0], qa[3][1], qa[3][2], qa[3][3], kb[6], kb[7]);
        }

        float tm0 = fmaxf(S[0][0], S[0][1]);
        float tm1 = fmaxf(S[0][2], S[0][3]);
        #pragma unroll
        for (int nc = 1; nc < 8; nc++) {
            tm0 = fmaxf(tm0, fmaxf(S[nc][0], S[nc][1]));
            tm1 = fmaxf(tm1, fmaxf(S[nc][2], S[nc][3]));
        }
        tm0 = fmaxf(tm0, __shfl_xor_sync(0xffffffffu, tm0, 1));
        tm0 = fmaxf(tm0, __shfl_xor_sync(0xffffffffu, tm0, 2));
        tm1 = fmaxf(tm1, __shfl_xor_sync(0xffffffffu, tm1, 1));
        tm1 = fmaxf(tm1, __shfl_xor_sync(0xffffffffu, tm1, 2));
        float nm0 = fmaxf(mrow0, tm0), nm1 = fmaxf(mrow1, tm1);
        float sc0 = exp2f((mrow0 - nm0) * 1.44269504f);
        float sc1 = exp2f((mrow1 - nm1) * 1.44269504f);
        mrow0 = nm0; mrow1 = nm1;
        float c0 = 1064866805.0f - nm0 * 12102203.16f;
        float c1 = 1064866805.0f - nm1 * 12102203.16f;

        unsigned P[4][4];
        #pragma unroll
        for (int jc = 0; jc < 4; jc++) {
            P[jc][0] = packh2(sexp(S[2*jc][0],   c0), sexp(S[2*jc][1],   c0));
            P[jc][1] = packh2(sexp(S[2*jc][2],   c1), sexp(S[2*jc][3],   c1));
            P[jc][2] = packh2(sexp(S[2*jc+1][0], c0), sexp(S[2*jc+1][1], c0));
            P[jc][3] = packh2(sexp(S[2*jc+1][2], c1), sexp(S[2*jc+1][3], c1));
        }

        float lf[4] = {0.0f, 0.0f, 0.0f, 0.0f};
        #pragma unroll
        for (int jc = 0; jc < 4; jc++)
            mma16816(lf, P[jc][0], P[jc][1], P[jc][2], P[jc][3], ONES, ONES);
        lrow0 = lrow0 * sc0 + lf[0];
        lrow1 = lrow1 * sc1 + lf[2];

        #pragma unroll
        for (int dc = 0; dc < 8; dc++) {
            Of[dc][0] *= sc0; Of[dc][1] *= sc0;
            Of[dc][2] *= sc1; Of[dc][3] *= sc1;
        }

        #pragma unroll
        for (int jc = 0; jc < 4; jc++) {
            int vrow = jc * 16 + (lane & 15);
            int vcb  = (lane >> 4) * 8;
            #pragma unroll
            for (int dcp = 0; dcp < 4; dcp++) {
                unsigned vb[4];
                ldm4t(vb, vsb + (vrow * SM_STRIDE + dcp * 16 + vcb) * 2);
                mma16816(Of[2*dcp],     P[jc][0], P[jc][1], P[jc][2], P[jc][3], vb[0], vb[1]);
                mma16816(Of[2*dcp + 1], P[jc][0], P[jc][1], P[jc][2], P[jc][3], vb[2], vb[3]);
            }
        }

        if (it + 1 < 64) {
            asm volatile("cp.async.wait_group 0;\n");
            __syncthreads();
        }
    }

    float inv0 = 1.0f / lrow0, inv1 = 1.0f / lrow1;
    int m = m0 + (w << 4) + gid;
    #pragma unroll
    for (int dc = 0; dc < 8; dc++) {
        int d0 = dc * 8 + tig * 2;
        g_O[(b * 64 + d0)     * NDS + m]     = Of[dc][0] * inv0;
        g_O[(b * 64 + d0 + 1) * NDS + m]     = Of[dc][1] * inv0;
        g_O[(b * 64 + d0)     * NDS + m + 8] = Of[dc][2] * inv1;
        g_O[(b * 64 + d0 + 1) * NDS + m + 8] = Of[dc][3] * inv1;
    }
}

// ============================================================================
// K4: convout — full-res conv0 (f16 hi/lo 3-pass) + fused epilogue.
// ============================================================================
#define CO_OFF_WH  0
#define CO_OFF_WL  25600
#define CO_OFF_ACT 51200
#define CO_ACT_BUF 16896
#define CONVOUT_SMEM (51200 + 2 * 17408)

__global__ __launch_bounds__(256, 2) void convout_kernel(
    const float* __restrict__ x1, const float* __restrict__ x2,
    const float* __restrict__ w,  const float* __restrict__ bias,
    const float* __restrict__ gamma, float* __restrict__ out)
{
    extern __shared__ char smc[];
    __half* WH = (__half*)(smc + CO_OFF_WH);
    __half* WL = (__half*)(smc + CO_OFF_WL);
    unsigned smu = (unsigned)__cvta_generic_to_shared(smc);

    int t = threadIdx.x;
    int lane = t & 31, wp = t >> 5;
    int ln15 = lane & 15, hb8 = (lane >> 4) * 8;
    int y = blockIdx.x, b = blockIdx.y;
    int p0 = y << 8;
    int ndbase = (y >> 2) << 6;

    for (int i = t; i < 12288; i += 256) {
        int o = i / 192, c = i - o * 192;
        float v = w[i];
        __half h = __float2half_rn(v);
        WH[o * 200 + c] = h;
        WL[o * 200 + c] = __float2half_rn(v - __half2float(h));
    }

    int r = t >> 4, col0 = (t & 15) << 4;
    float f[16];
    {
        const float* s = x1 + (size_t)(b * 128 + r) * HW + p0 + col0;
        #pragma unroll
        for (int j = 0; j < 4; j++) *(float4*)&f[4*j] = *(const float4*)(s + 4*j);
        unsigned H[8], L[8];
        #pragma unroll
        for (int j = 0; j < 8; j++) {
            __half h0 = __float2half_rn(f[2*j]), h1 = __float2half_rn(f[2*j+1]);
            H[j] = hpack(h0, h1);
            L[j] = hpack(__float2half_rn(f[2*j]   - __half2float(h0)),
                         __float2half_rn(f[2*j+1] - __half2float(h1)));
        }
        __half* AH = (__half*)(smc + CO_OFF_ACT);
        __half* AL = AH + 4224;
        *(uint4*)&AH[r * 264 + col0]     = make_uint4(H[0], H[1], H[2], H[3]);
        *(uint4*)&AH[r * 264 + col0 + 8] = make_uint4(H[4], H[5], H[6], H[7]);
        *(uint4*)&AL[r * 264 + col0]     = make_uint4(L[0], L[1], L[2], L[3]);
        *(uint4*)&AL[r * 264 + col0 + 8] = make_uint4(L[4], L[5], L[6], L[7]);
    }
    __syncthreads();

    float acc[4][4][4];
    #pragma unroll
    for (int mt = 0; mt < 4; mt++)
        #pragma unroll
        for (int nb = 0; nb < 4; nb++)
            #pragma unroll
            for (int q = 0; q < 4; q++) acc[mt][nb][q] = 0.0f;

    unsigned whB = smu + CO_OFF_WH + (ln15 * 200 + hb8) * 2;
    unsigned wlB = smu + CO_OFF_WL + (ln15 * 200 + hb8) * 2;

    #pragma unroll 1
    for (int ks = 0; ks < 12; ks++) {
        if (ks < 11) {
            int c = (ks + 1) * 16 + r;
            const float* s = (c < 128) ? x1 + (size_t)(b * 128 + c) * HW
                                       : x2 + (size_t)(b * 64 + c - 128) * HW;
            s += p0 + col0;
            #pragma unroll
            for (int j = 0; j < 4; j++) *(float4*)&f[4*j] = *(const float4*)(s + 4*j);
        }

        int bf = ks & 1;
        unsigned actH = smu + CO_OFF_ACT + bf * CO_ACT_BUF +
                        (ln15 * 264 + wp * 32 + hb8) * 2;
        unsigned actL = actH + 4224 * 2;

        unsigned A[4][4], Bh[8], Bl[8];
        ldm4t(Bh,     actH);
        ldm4t(Bh + 4, actH + 32);
        ldm4t(Bl,     actL);
        ldm4t(Bl + 4, actL + 32);
        #pragma unroll
        for (int mt = 0; mt < 4; mt++)
            ldm4(A[mt], whB + mt * 6400 + ks * 32);
        #pragma unroll
        for (int mt = 0; mt < 4; mt++) {
            mma16816(acc[mt][0], A[mt][0], A[mt][1], A[mt][2], A[mt][3], Bh[0], Bh[1]);
            mma16816(acc[mt][1], A[mt][0], A[mt][1], A[mt][2], A[mt][3], Bh[2], Bh[3]);
            mma16816(acc[mt][2], A[mt][0], A[mt][1], A[mt][2], A[mt][3], Bh[4], Bh[5]);
            mma16816(acc[mt][3], A[mt][0], A[mt][1], A[mt][2], A[mt][3], Bh[6], Bh[7]);
            mma16816(acc[mt][0], A[mt][0], A[mt][1], A[mt][2], A[mt][3], Bl[0], Bl[1]);
            mma16816(acc[mt][1], A[mt][0], A[mt][1], A[mt][2], A[mt][3], Bl[2], Bl[3]);
            mma16816(acc[mt][2], A[mt][0], A[mt][1], A[mt][2], A[mt][3], Bl[4], Bl[5]);
            mma16816(acc[mt][3], A[mt][0], A[mt][1], A[mt][2], A[mt][3], Bl[6], Bl[7]);
        }
        #pragma unroll
        for (int mt = 0; mt < 4; mt++)
            ldm4(A[mt], wlB + mt * 6400 + ks * 32);
        #pragma unroll
        for (int mt = 0; mt < 4; mt++) {
            mma16816(acc[mt][0], A[mt][0], A[mt][1], A[mt][2], A[mt][3], Bh[0], Bh[1]);
            mma16816(acc[mt][1], A[mt][0], A[mt][1], A[mt][2], A[mt][3], Bh[2], Bh[3]);
            mma16816(acc[mt][2], A[mt][0], A[mt][1], A[mt][2], A[mt][3], Bh[4], Bh[5]);
            mma16816(acc[mt][3], A[mt][0], A[mt][1], A[mt][2], A[mt][3], Bh[6], Bh[7]);
        }

        if (ks < 11) {
            unsigned H[8], L[8];
            #pragma unroll
            for (int j = 0; j < 8; j++) {
                __half h0 = __float2half_rn(f[2*j]), h1 = __float2half_rn(f[2*j+1]);
                H[j] = hpack(h0, h1);
                L[j] = hpack(__float2half_rn(f[2*j]   - __half2float(h0)),
                             __float2half_rn(f[2*j+1] - __half2float(h1)));
            }
            __half* AH = (__half*)(smc + CO_OFF_ACT + (bf ^ 1) * CO_ACT_BUF);
            __half* AL = AH + 4224;
            *(uint4*)&AH[r * 264 + col0]     = make_uint4(H[0], H[1], H[2], H[3]);
            *(uint4*)&AH[r * 264 + col0 + 8] = make_uint4(H[4], H[5], H[6], H[7]);
            *(uint4*)&AL[r * 264 + col0]     = make_uint4(L[0], L[1], L[2], L[3]);
            *(uint4*)&AL[r * 264 + col0 + 8] = make_uint4(L[4], L[5], L[6], L[7]);
            __syncthreads();
        }
    }

    float ov[16], evv[16];
    {
        int o = t >> 2, c0 = (t & 3) << 4;
        const float* po = g_O   + (size_t)(b * 64 + o) * NDS + ndbase + c0;
        const float* pe = g_efd + (size_t)(b * 64 + o) * NDS + ndbase + c0;
        #pragma unroll
        for (int j = 0; j < 4; j++) {
            *(float4*)&ov[4*j]  = *(const float4*)(po + 4*j);
            *(float4*)&evv[4*j] = *(const float4*)(pe + 4*j);
        }
    }
    __syncthreads();

    float* OS = (float*)(smc + CO_OFF_ACT);
    float* ES = OS + 64 * 68;
    {
        int o = t >> 2, c0 = (t & 3) << 4;
        #pragma unroll
        for (int j = 0; j < 4; j++) {
            *(float4*)&OS[o * 68 + c0 + 4*j] = *(const float4*)&ov[4*j];
            *(float4*)&ES[o * 68 + c0 + 4*j] = *(const float4*)&evv[4*j];
        }
    }
    __syncthreads();

    float tg = THITA_F * __ldg(gamma);
    int g = lane >> 2, tig = lane & 3;
    #pragma unroll
    for (int mt = 0; mt < 4; mt++) {
        int o = mt * 16 + g;
        float bb0 = __ldg(&bias[o]), bb1 = __ldg(&bias[o + 8]);
        #pragma unroll
        for (int nb = 0; nb < 4; nb++) {
            int px = wp * 32 + nb * 8 + tig * 2;
            int ndc = px >> 2;
            float a0 = tg * OS[o * 68 + ndc];
            float a1 = tg * OS[(o + 8) * 68 + ndc];
            float2 r0 = make_float2(fmaxf(acc[mt][nb][0] + bb0, 0.0f) + a0,
                                    fmaxf(acc[mt][nb][1] + bb0, 0.0f) + a0);
            float2 r1 = make_float2(fmaxf(acc[mt][nb][2] + bb1, 0.0f) + a1,
                                    fmaxf(acc[mt][nb][3] + bb1, 0.0f) + a1);
            *(float2*)(out + (size_t)(b * 64 + o)     * HW + p0 + px) = r0;
            *(float2*)(out + (size_t)(b * 64 + o + 8) * HW + p0 + px) = r1;
        }
    }

    int xq = t & 63;
    #pragma unroll
    for (int rep = 0; rep < 16; rep++) {
        int o = rep * 4 + (t >> 6);
        float v = ES[o * 68 + xq];
        *(float4*)(out + OUT2OFF + (size_t)(b * 64 + o) * HW + p0 + (xq << 2)) =
            make_float4(v, v, v, v);
    }
}

// ============================================================================
extern "C" void kernel_launch(void* const* d_in, const int* in_sizes, int n_in,
                              void* d_out, int out_size)
{
    const float* x1    = (const float*)d_in[0];
    const float* x2    = (const float*)d_in[1];
    const float* ev    = (const float*)d_in[2];
    const float* xw0   = (const float*)d_in[3];
    const float* xb0   = (const float*)d_in[4];
    const float* xw1   = (const float*)d_in[5];
    const float* xb1   = (const float*)d_in[6];
    const float* ew0   = (const float*)d_in[7];
    const float* eb0   = (const float*)d_in[8];
    const float* ew1   = (const float*)d_in[9];
    const float* eb1   = (const float*)d_in[10];
    const float* qw    = (const float*)d_in[11];
    const float* qb    = (const float*)d_in[12];
    const float* kw    = (const float*)d_in[13];
    const float* kb    = (const float*)d_in[14];
    const float* vw    = (const float*)d_in[15];
    const float* vb    = (const float*)d_in[16];
    const float* gamma = (const float*)d_in[17];
    float* out = (float*)d_out;

    cudaFuncSetAttribute(prep_kernel,
                         cudaFuncAttributeMaxDynamicSharedMemorySize, PREP_SMEM);
    cudaFuncSetAttribute(qkv_kernel,
                         cudaFuncAttributeMaxDynamicSharedMemorySize, QKV_SMEM);
    cudaFuncSetAttribute(attn_kernel,
                         cudaFuncAttributeMaxDynamicSharedMemorySize, ATTN_SMEM);
    cudaFuncSetAttribute(convout_kernel,
                         cudaFuncAttributeMaxDynamicSharedMemorySize, CONVOUT_SMEM);

    prep_kernel<<<dim3(NDS / 64, BATCH, 2), 128, PREP_SMEM>>>(
        x1, x2, ev, xw0, xb0, ew0, eb0, ew1, eb1);
    qkv_kernel<<<dim3(NDS / 64, BATCH), 128, QKV_SMEM>>>(
        xw1, xb1, qw, qb, kw, kb, vw, vb);
    attn_kernel<<<dim3(NDS / 128, BATCH), 256, ATTN_SMEM>>>();
    convout_kernel<<<dim3(256, BATCH), 256, CONVOUT_SMEM>>>(
        x1, x2, xw0, xb0, gamma, out);
}

// round 7
// speedup vs baseline: 1.3370x; 1.0897x over previous
#include <cuda_runtime.h>
#include <cuda_fp16.h>
#include <math.h>

#define BATCH 4
#define CHN 64
#define HW 65536        // 256*256
#define NDS 4096        // 64*64 downsampled pixels
#define THITA_F 1.0e-4f
#define OUT2OFF (BATCH * CHN * HW)

// ---------------- scratch (device globals) ----------------------------------
__device__ __half g_xdsh[BATCH * CHN * NDS];    // down4(x) f16 [b][c][n]
__device__ float  g_efd [BATCH * CHN * NDS];    // ef ds fp32 [b][c][n] (feeds ef_up)
__device__ __half g_efdh[BATCH * CHN * NDS];    // ef ds f16 [b][c][n] (feeds k conv)
__device__ __half g_qh[BATCH * NDS * CHN];      // [b][n][d] f16
__device__ __half g_kh[BATCH * NDS * CHN];
__device__ __half g_vh[BATCH * NDS * CHN];
__device__ float  g_O[BATCH * CHN * NDS];       // attention output [b][d][m]

// ============================================================================
// mma / ldmatrix helpers
// ============================================================================
__device__ __forceinline__ void mma16816(float* d,
    unsigned a0, unsigned a1, unsigned a2, unsigned a3,
    unsigned b0, unsigned b1)
{
    asm volatile(
        "mma.sync.aligned.m16n8k16.row.col.f32.f16.f16.f32 "
        "{%0,%1,%2,%3}, {%4,%5,%6,%7}, {%8,%9}, {%0,%1,%2,%3};\n"
        : "+f"(d[0]), "+f"(d[1]), "+f"(d[2]), "+f"(d[3])
        : "r"(a0), "r"(a1), "r"(a2), "r"(a3), "r"(b0), "r"(b1));
}
__device__ __forceinline__ void ldm4(unsigned* r, unsigned a) {
    asm volatile("ldmatrix.sync.aligned.m8n8.x4.shared.b16 {%0,%1,%2,%3}, [%4];\n"
        : "=r"(r[0]), "=r"(r[1]), "=r"(r[2]), "=r"(r[3]) : "r"(a));
}
__device__ __forceinline__ void ldm4t(unsigned* r, unsigned a) {
    asm volatile("ldmatrix.sync.aligned.m8n8.x4.trans.shared.b16 {%0,%1,%2,%3}, [%4];\n"
        : "=r"(r[0]), "=r"(r[1]), "=r"(r[2]), "=r"(r[3]) : "r"(a));
}
__device__ __forceinline__ void cpasync16(unsigned dst, const void* src) {
    asm volatile("cp.async.cg.shared.global [%0], [%1], 16;\n"
        :: "r"(dst), "l"(src));
}
__device__ __forceinline__ unsigned hpack(__half a, __half b) {
    __half2 h = __halves2half2(a, b);
    return *(unsigned*)&h;
}
__device__ __forceinline__ unsigned packh2(float a, float b) {
    __half2 h = __floats2half2_rn(a, b);
    return *(unsigned*)&h;
}
__device__ __forceinline__ float sexp(float s, float c) {
    float t = fmaf(s, 12102203.16f, c);
    t = fmaxf(t, 0.0f);
    return __int_as_float(__float2int_rn(t));
}

// single-pass f16 GEMM: acc[8][4] += W(16 rows at wb) @ act(K=16*nks x 64, stride 72)
__device__ __forceinline__ void gemm1p(float acc[8][4], unsigned wb, int wstride,
                                       unsigned ab, int nks, int lane)
{
    int ln15 = lane & 15, hb8 = (lane >> 4) * 8;
    unsigned wl = wb + (ln15 * wstride + hb8) * 2;
    #pragma unroll
    for (int ks = 0; ks < nks; ks++) {
        unsigned al = ab + ((ks * 16 + ln15) * 72 + hb8) * 2;
        unsigned B[16], A[4];
        ldm4t(B,      al);
        ldm4t(B + 4,  al + 32);
        ldm4t(B + 8,  al + 64);
        ldm4t(B + 12, al + 96);
        ldm4(A, wl + ks * 32);
        #pragma unroll
        for (int nc = 0; nc < 8; nc++) {
            int ib = (nc >> 1) * 4 + (nc & 1) * 2;
            mma16816(acc[nc], A[0], A[1], A[2], A[3], B[ib], B[ib + 1]);
        }
    }
}

// 3-pass hi/lo GEMM (K=64): acc += Wh@Ah + Wh@Al + Wl@Ah
__device__ __forceinline__ void gemm3p(float acc[8][4],
    unsigned wh, unsigned wlo, unsigned ah, unsigned alo, int lane)
{
    int ln15 = lane & 15, hb8 = (lane >> 4) * 8;
    unsigned wbh = wh  + (ln15 * 72 + hb8) * 2;
    unsigned wbl = wlo + (ln15 * 72 + hb8) * 2;
    #pragma unroll
    for (int ks = 0; ks < 4; ks++) {
        unsigned abh = ah  + ((ks * 16 + ln15) * 72 + hb8) * 2;
        unsigned abl = alo + ((ks * 16 + ln15) * 72 + hb8) * 2;
        unsigned Bh[16], Bl[16], Wf[4], Lf[4];
        ldm4t(Bh,      abh);
        ldm4t(Bh + 4,  abh + 32);
        ldm4t(Bh + 8,  abh + 64);
        ldm4t(Bh + 12, abh + 96);
        ldm4t(Bl,      abl);
        ldm4t(Bl + 4,  abl + 32);
        ldm4t(Bl + 8,  abl + 64);
        ldm4t(Bl + 12, abl + 96);
        ldm4(Wf, wbh + ks * 32);
        ldm4(Lf, wbl + ks * 32);
        #pragma unroll
        for (int nc = 0; nc < 8; nc++) {
            int ib = (nc >> 1) * 4 + (nc & 1) * 2;
            mma16816(acc[nc], Wf[0], Wf[1], Wf[2], Wf[3], Bh[ib], Bh[ib + 1]);
            mma16816(acc[nc], Wf[0], Wf[1], Wf[2], Wf[3], Bl[ib], Bl[ib + 1]);
            mma16816(acc[nc], Lf[0], Lf[1], Lf[2], Lf[3], Bh[ib], Bh[ib + 1]);
        }
    }
}

// ============================================================================
// K1: prep — z=0: conv0_ds (f16 1-pass, 192->64) -> g_xdsh
//            z=1: ef chain (f16 hi/lo 3-pass, 64->64 twice) -> g_efd, g_efdh
// ============================================================================
#define PREP_SMEM (64 * 200 * 2 + 192 * 72 * 2)   // 53248

__global__ __launch_bounds__(128) void prep_kernel(
    const float* __restrict__ x1, const float* __restrict__ x2,
    const float* __restrict__ ev,
    const float* __restrict__ xw0, const float* __restrict__ xb0,
    const float* __restrict__ ew0, const float* __restrict__ eb0,
    const float* __restrict__ ew1, const float* __restrict__ eb1)
{
    extern __shared__ char smc[];
    unsigned smu = (unsigned)__cvta_generic_to_shared(smc);
    int t = threadIdx.x, lane = t & 31, w = t >> 5;
    int gid = lane >> 2, tig = lane & 3;
    int blk = blockIdx.x, b = blockIdx.y;
    int n0 = blk << 6;

    float acc[8][4];
    #pragma unroll
    for (int nc = 0; nc < 8; nc++)
        #pragma unroll
        for (int q = 0; q < 4; q++) acc[nc][q] = 0.0f;

    if (blockIdx.z == 0) {
        __half* W  = (__half*)smc;
        __half* Ac = (__half*)(smc + 64 * 200 * 2);
        for (int i = t; i < 12288; i += 128) {
            int o = i / 192, c = i - o * 192;
            W[o * 200 + c] = __float2half_rn(xw0[i]);
        }
        for (int i = t; i < 12288; i += 128) {
            int c = i >> 6, x = i & 63;
            const float* s = (c < 128) ? x1 + (size_t)(b * 128 + c) * HW
                                       : x2 + (size_t)(b * 64 + c - 128) * HW;
            Ac[c * 72 + x] = __float2half_rn(s[(blk << 10) + (x << 2)]);
        }
        __syncthreads();

        gemm1p(acc, smu + (w * 16) * 200 * 2, 200,
               smu + 64 * 200 * 2, 12, lane);

        int o = (w << 4) + gid;
        float b0 = __ldg(&xb0[o]), b1 = __ldg(&xb0[o + 8]);
        #pragma unroll
        for (int nc = 0; nc < 8; nc++) {
            int n = n0 + nc * 8 + tig * 2;
            *(__half2*)&g_xdsh[(size_t)(b * 64 + o) * NDS + n] =
                __floats2half2_rn(fmaxf(acc[nc][0] + b0, 0.0f),
                                  fmaxf(acc[nc][1] + b0, 0.0f));
            *(__half2*)&g_xdsh[(size_t)(b * 64 + o + 8) * NDS + n] =
                __floats2half2_rn(fmaxf(acc[nc][2] + b1, 0.0f),
                                  fmaxf(acc[nc][3] + b1, 0.0f));
        }
    } else {
        __half* Wh = (__half*)smc;
        __half* Wl = Wh + 64 * 72;
        __half* Ah = Wl + 64 * 72;
        __half* Al = Ah + 64 * 72;
        unsigned oWh = smu, oWl = smu + 9216, oAh = smu + 18432, oAl = smu + 27648;

        for (int i = t; i < 4096; i += 128) {
            float v = ew0[i];
            __half h = __float2half_rn(v);
            int o = i >> 6, c = i & 63;
            Wh[o * 72 + c] = h;
            Wl[o * 72 + c] = __float2half_rn(v - __half2float(h));
        }
        for (int i = t; i < 4096; i += 128) {
            int c = i >> 6, x = i & 63;
            float v = ev[(size_t)(b * 64 + c) * HW + (blk << 10) + (x << 2)];
            __half h = __float2half_rn(v);
            Ah[c * 72 + x] = h;
            Al[c * 72 + x] = __float2half_rn(v - __half2float(h));
        }
        __syncthreads();

        gemm3p(acc, oWh + (w * 16) * 144, oWl + (w * 16) * 144, oAh, oAl, lane);
        __syncthreads();

        {
            int o = (w << 4) + gid;
            float b0 = __ldg(&eb0[o]), b1 = __ldg(&eb0[o + 8]);
            #pragma unroll
            for (int nc = 0; nc < 8; nc++) {
                int px = nc * 8 + tig * 2;
                float t0 = fmaxf(acc[nc][0] + b0, 0.0f);
                float t1 = fmaxf(acc[nc][1] + b0, 0.0f);
                float t2 = fmaxf(acc[nc][2] + b1, 0.0f);
                float t3 = fmaxf(acc[nc][3] + b1, 0.0f);
                __half h0 = __float2half_rn(t0), h1 = __float2half_rn(t1);
                __half h2 = __float2half_rn(t2), h3 = __float2half_rn(t3);
                *(__half2*)&Ah[o * 72 + px] = __halves2half2(h0, h1);
                *(__half2*)&Al[o * 72 + px] = __floats2half2_rn(
                    t0 - __half2float(h0), t1 - __half2float(h1));
                *(__half2*)&Ah[(o + 8) * 72 + px] = __halves2half2(h2, h3);
                *(__half2*)&Al[(o + 8) * 72 + px] = __floats2half2_rn(
                    t2 - __half2float(h2), t3 - __half2float(h3));
            }
        }
        for (int i = t; i < 4096; i += 128) {
            float v = ew1[i];
            __half h = __float2half_rn(v);
            int o = i >> 6, c = i & 63;
            Wh[o * 72 + c] = h;
            Wl[o * 72 + c] = __float2half_rn(v - __half2float(h));
        }
        __syncthreads();

        #pragma unroll
        for (int nc = 0; nc < 8; nc++)
            #pragma unroll
            for (int q = 0; q < 4; q++) acc[nc][q] = 0.0f;
        gemm3p(acc, oWh + (w * 16) * 144, oWl + (w * 16) * 144, oAh, oAl, lane);

        int o = (w << 4) + gid;
        float b0 = __ldg(&eb1[o]), b1 = __ldg(&eb1[o + 8]);
        #pragma unroll
        for (int nc = 0; nc < 8; nc++) {
            int n = n0 + nc * 8 + tig * 2;
            float r0 = fmaxf(acc[nc][0] + b0, 0.0f);
            float r1 = fmaxf(acc[nc][1] + b0, 0.0f);
            float r2 = fmaxf(acc[nc][2] + b1, 0.0f);
            float r3 = fmaxf(acc[nc][3] + b1, 0.0f);
            *(float2*)&g_efd[(size_t)(b * 64 + o) * NDS + n]     = make_float2(r0, r1);
            *(float2*)&g_efd[(size_t)(b * 64 + o + 8) * NDS + n] = make_float2(r2, r3);
            *(__half2*)&g_efdh[(size_t)(b * 64 + o) * NDS + n]     = __floats2half2_rn(r0, r1);
            *(__half2*)&g_efdh[(size_t)(b * 64 + o + 8) * NDS + n] = __floats2half2_rn(r2, r3);
        }
    }
}

// ============================================================================
// K2: qkv — all f16 1-pass mma (unchanged from round 6)
// ============================================================================
#define QKV_SMEM (4 * 64 * 72 * 2)

__global__ __launch_bounds__(128) void qkv_kernel(
    const float* __restrict__ xw1, const float* __restrict__ xb1,
    const float* __restrict__ qw,  const float* __restrict__ qb,
    const float* __restrict__ kw,  const float* __restrict__ kb,
    const float* __restrict__ vw,  const float* __restrict__ vb)
{
    extern __shared__ char smc[];
    unsigned smu = (unsigned)__cvta_generic_to_shared(smc);
    __half* W   = (__half*)smc;
    __half* Act = W + 64 * 72;
    __half* Tb  = Act + 64 * 72;
    __half* Tr  = Tb + 64 * 72;
    unsigned oW = smu, oAct = smu + 9216, oTb = smu + 18432;

    int t = threadIdx.x, lane = t & 31, w = t >> 5;
    int gid = lane >> 2, tig = lane & 3;
    int blk = blockIdx.x, b = blockIdx.y;
    int n0 = blk << 6;
    int o = (w << 4) + gid;

    for (int i = t; i < 512; i += 128) {
        int row = i >> 3, off = i & 7;
        *(uint4*)&Act[row * 72 + off * 8] =
            *(const uint4*)&g_xdsh[(size_t)(b * 64 + row) * NDS + n0 + off * 8];
    }
    for (int i = t; i < 4096; i += 128)
        W[(i >> 6) * 72 + (i & 63)] = __float2half_rn(xw1[i]);
    __syncthreads();

    float acc[8][4];
    #pragma unroll
    for (int nc = 0; nc < 8; nc++)
        #pragma unroll
        for (int q = 0; q < 4; q++) acc[nc][q] = 0.0f;
    gemm1p(acc, oW + (w * 16) * 144, 72, oAct, 4, lane);
    {
        float b0 = __ldg(&xb1[o]), b1 = __ldg(&xb1[o + 8]);
        #pragma unroll
        for (int nc = 0; nc < 8; nc++) {
            int px = nc * 8 + tig * 2;
            *(__half2*)&Tb[o * 72 + px] = __floats2half2_rn(
                fmaxf(acc[nc][0] + b0, 0.0f), fmaxf(acc[nc][1] + b0, 0.0f));
            *(__half2*)&Tb[(o + 8) * 72 + px] = __floats2half2_rn(
                fmaxf(acc[nc][2] + b1, 0.0f), fmaxf(acc[nc][3] + b1, 0.0f));
        }
    }
    __syncthreads();
    for (int i = t; i < 4096; i += 128)
        W[(i >> 6) * 72 + (i & 63)] = __float2half_rn(qw[i]);
    __syncthreads();

    #pragma unroll
    for (int nc = 0; nc < 8; nc++)
        #pragma unroll
        for (int q = 0; q < 4; q++) acc[nc][q] = 0.0f;
    gemm1p(acc, oW + (w * 16) * 144, 72, oTb, 4, lane);
    {
        float b0 = __ldg(&qb[o]), b1 = __ldg(&qb[o + 8]);
        #pragma unroll
        for (int nc = 0; nc < 8; nc++) {
            int px = nc * 8 + tig * 2;
            Tr[px * 72 + o]           = __float2half_rn(fmaxf(acc[nc][0] + b0, 0.0f));
            Tr[(px + 1) * 72 + o]     = __float2half_rn(fmaxf(acc[nc][1] + b0, 0.0f));
            Tr[px * 72 + o + 8]       = __float2half_rn(fmaxf(acc[nc][2] + b1, 0.0f));
            Tr[(px + 1) * 72 + o + 8] = __float2half_rn(fmaxf(acc[nc][3] + b1, 0.0f));
        }
    }
    __syncthreads();
    for (int i = t; i < 512; i += 128) {
        int row = i >> 3, off = i & 7;
        *(uint4*)&g_qh[((size_t)b * NDS + n0 + row) * 64 + off * 8] =
            *(uint4*)&Tr[row * 72 + off * 8];
    }
    for (int i = t; i < 4096; i += 128)
        W[(i >> 6) * 72 + (i & 63)] = __float2half_rn(vw[i]);
    __syncthreads();

    #pragma unroll
    for (int nc = 0; nc < 8; nc++)
        #pragma unroll
        for (int q = 0; q < 4; q++) acc[nc][q] = 0.0f;
    gemm1p(acc, oW + (w * 16) * 144, 72, oTb, 4, lane);
    {
        float b0 = __ldg(&vb[o]), b1 = __ldg(&vb[o + 8]);
        #pragma unroll
        for (int nc = 0; nc < 8; nc++) {
            int px = nc * 8 + tig * 2;
            Tr[px * 72 + o]           = __float2half_rn(fmaxf(acc[nc][0] + b0, 0.0f));
            Tr[(px + 1) * 72 + o]     = __float2half_rn(fmaxf(acc[nc][1] + b0, 0.0f));
            Tr[px * 72 + o + 8]       = __float2half_rn(fmaxf(acc[nc][2] + b1, 0.0f));
            Tr[(px + 1) * 72 + o + 8] = __float2half_rn(fmaxf(acc[nc][3] + b1, 0.0f));
        }
    }
    __syncthreads();
    for (int i = t; i < 512; i += 128) {
        int row = i >> 3, off = i & 7;
        *(uint4*)&g_vh[((size_t)b * NDS + n0 + row) * 64 + off * 8] =
            *(uint4*)&Tr[row * 72 + off * 8];
    }
    for (int i = t; i < 4096; i += 128)
        W[(i >> 6) * 72 + (i & 63)] = __float2half_rn(kw[i]);
    for (int i = t; i < 512; i += 128) {
        int row = i >> 3, off = i & 7;
        *(uint4*)&Act[row * 72 + off * 8] =
            *(const uint4*)&g_efdh[(size_t)(b * 64 + row) * NDS + n0 + off * 8];
    }
    __syncthreads();

    #pragma unroll
    for (int nc = 0; nc < 8; nc++)
        #pragma unroll
        for (int q = 0; q < 4; q++) acc[nc][q] = 0.0f;
    gemm1p(acc, oW + (w * 16) * 144, 72, oAct, 4, lane);
    {
        float b0 = __ldg(&kb[o]), b1 = __ldg(&kb[o + 8]);
        #pragma unroll
        for (int nc = 0; nc < 8; nc++) {
            int px = nc * 8 + tig * 2;
            Tr[px * 72 + o]           = __float2half_rn(fmaxf(acc[nc][0] + b0, 0.0f));
            Tr[(px + 1) * 72 + o]     = __float2half_rn(fmaxf(acc[nc][1] + b0, 0.0f));
            Tr[px * 72 + o + 8]       = __float2half_rn(fmaxf(acc[nc][2] + b1, 0.0f));
            Tr[(px + 1) * 72 + o + 8] = __float2half_rn(fmaxf(acc[nc][3] + b1, 0.0f));
        }
    }
    __syncthreads();
    for (int i = t; i < 512; i += 128) {
        int row = i >> 3, off = i & 7;
        *(uint4*)&g_kh[((size_t)b * NDS + n0 + row) * 64 + off * 8] =
            *(uint4*)&Tr[row * 72 + off * 8];
    }
}

// ============================================================================
// K3: flash attention (unchanged round-3 config)
// ============================================================================
#define SM_STRIDE 72
#define ATTN_SMEM ((128 * SM_STRIDE + 4 * 64 * SM_STRIDE) * 2)

__global__ __launch_bounds__(256, 1) void attn_kernel()
{
    extern __shared__ __half smh[];
    __half* qs  = smh;
    __half* ks0 = smh + 128 * SM_STRIDE;
    __half* vs0 = ks0 + 2 * 64 * SM_STRIDE;

    int tid  = threadIdx.x;
    int lane = tid & 31, w = tid >> 5;
    int gid  = lane >> 2, tig = lane & 3;
    int b    = blockIdx.y;
    int m0   = blockIdx.x << 7;

    const __half* qg = g_qh + (size_t)b * NDS * 64;
    const __half* kg = g_kh + (size_t)b * NDS * 64;
    const __half* vg = g_vh + (size_t)b * NDS * 64;

    unsigned qs_base = (unsigned)__cvta_generic_to_shared(qs);
    unsigned ks_base = (unsigned)__cvta_generic_to_shared(ks0);
    unsigned vs_base = (unsigned)__cvta_generic_to_shared(vs0);

    #pragma unroll
    for (int rep = 0; rep < 2; rep++) {
        int c = tid + rep * 256;
        int row = c >> 3, off = c & 7;
        cpasync16(ks_base + (row * SM_STRIDE + off * 8) * 2, kg + row * 64 + off * 8);
        cpasync16(vs_base + (row * SM_STRIDE + off * 8) * 2, vg + row * 64 + off * 8);
    }
    asm volatile("cp.async.commit_group;\n");

    for (int c = tid; c < 1024; c += 256) {
        int row = c >> 3, off = c & 7;
        *(uint4*)(qs + row * SM_STRIDE + off * 8) =
            *(const uint4*)(qg + (size_t)(m0 + row) * 64 + off * 8);
    }
    asm volatile("cp.async.wait_group 0;\n");
    __syncthreads();

    unsigned qa[4][4];
    {
        int row = (w << 4) + (lane & 15);
        #pragma unroll
        for (int kc = 0; kc < 4; kc++) {
            int dof = kc * 16 + (lane >> 4) * 8;
            ldm4(qa[kc], qs_base + (row * SM_STRIDE + dof) * 2);
        }
    }

    float Of[8][4];
    #pragma unroll
    for (int dc = 0; dc < 8; dc++)
        #pragma unroll
        for (int q = 0; q < 4; q++) Of[dc][q] = 0.0f;
    float mrow0 = -1e30f, mrow1 = -1e30f, lrow0 = 0.0f, lrow1 = 0.0f;
    const unsigned ONES = 0x3C003C00u;

    for (int it = 0; it < 64; it++) {
        int bf = it & 1;
        unsigned ksb = ks_base + bf * 64 * SM_STRIDE * 2;
        unsigned vsb = vs_base + bf * 64 * SM_STRIDE * 2;

        if (it + 1 < 64) {
            int n0n = (it + 1) << 6;
            int nb  = (it + 1) & 1;
            #pragma unroll
            for (int rep = 0; rep < 2; rep++) {
                int c = tid + rep * 256;
                int row = c >> 3, off = c & 7;
                cpasync16(ks_base + (nb * 64 * SM_STRIDE + row * SM_STRIDE + off * 8) * 2,
                          kg + (size_t)(n0n + row) * 64 + off * 8);
                cpasync16(vs_base + (nb * 64 * SM_STRIDE + row * SM_STRIDE + off * 8) * 2,
                          vg + (size_t)(n0n + row) * 64 + off * 8);
            }
            asm volatile("cp.async.commit_group;\n");
        }

        float S[8][4];
        #pragma unroll
        for (int nc = 0; nc < 8; nc++) {
            unsigned kb[8];
            int krow = nc * 8 + (lane & 7);
            int kd   = (lane >> 3) * 8;
            ldm4(kb,     ksb + (krow * SM_STRIDE + kd) * 2);
            ldm4(kb + 4, ksb + (krow * SM_STRIDE + 32 + kd) * 2);
            #pragma unroll
            for (int q = 0; q < 4; q++) S[nc][q] = 0.0f;
            mma16816(S[nc], qa[0][0], qa[0][1], qa[0][2], qa[0][3], kb[0], kb[1]);
            mma16816(S[nc], qa[1][0], qa[1][1], qa[1][2], qa[1][3], kb[2], kb[3]);
            mma16816(S[nc], qa[2][0], qa[2][1], qa[2][2], qa[2][3], kb[4], kb[5]);
            mma16816(S[nc], qa[3][0], qa[3][1], qa[3][2], qa[3][3], kb[6], kb[7]);
        }

        float tm0 = fmaxf(S[0][0], S[0][1]);
        float tm1 = fmaxf(S[0][2], S[0][3]);
        #pragma unroll
        for (int nc = 1; nc < 8; nc++) {
            tm0 = fmaxf(tm0, fmaxf(S[nc][0], S[nc][1]));
            tm1 = fmaxf(tm1, fmaxf(S[nc][2], S[nc][3]));
        }
        tm0 = fmaxf(tm0, __shfl_xor_sync(0xffffffffu, tm0, 1));
        tm0 = fmaxf(tm0, __shfl_xor_sync(0xffffffffu, tm0, 2));
        tm1 = fmaxf(tm1, __shfl_xor_sync(0xffffffffu, tm1, 1));
        tm1 = fmaxf(tm1, __shfl_xor_sync(0xffffffffu, tm1, 2));
        float nm0 = fmaxf(mrow0, tm0), nm1 = fmaxf(mrow1, tm1);
        float sc0 = exp2f((mrow0 - nm0) * 1.44269504f);
        float sc1 = exp2f((mrow1 - nm1) * 1.44269504f);
        mrow0 = nm0; mrow1 = nm1;
        float c0 = 1064866805.0f - nm0 * 12102203.16f;
        float c1 = 1064866805.0f - nm1 * 12102203.16f;

        unsigned P[4][4];
        #pragma unroll
        for (int jc = 0; jc < 4; jc++) {
            P[jc][0] = packh2(sexp(S[2*jc][0],   c0), sexp(S[2*jc][1],   c0));
            P[jc][1] = packh2(sexp(S[2*jc][2],   c1), sexp(S[2*jc][3],   c1));
            P[jc][2] = packh2(sexp(S[2*jc+1][0], c0), sexp(S[2*jc+1][1], c0));
            P[jc][3] = packh2(sexp(S[2*jc+1][2], c1), sexp(S[2*jc+1][3], c1));
        }

        float lf[4] = {0.0f, 0.0f, 0.0f, 0.0f};
        #pragma unroll
        for (int jc = 0; jc < 4; jc++)
            mma16816(lf, P[jc][0], P[jc][1], P[jc][2], P[jc][3], ONES, ONES);
        lrow0 = lrow0 * sc0 + lf[0];
        lrow1 = lrow1 * sc1 + lf[2];

        #pragma unroll
        for (int dc = 0; dc < 8; dc++) {
            Of[dc][0] *= sc0; Of[dc][1] *= sc0;
            Of[dc][2] *= sc1; Of[dc][3] *= sc1;
        }

        #pragma unroll
        for (int jc = 0; jc < 4; jc++) {
            int vrow = jc * 16 + (lane & 15);
            int vcb  = (lane >> 4) * 8;
            #pragma unroll
            for (int dcp = 0; dcp < 4; dcp++) {
                unsigned vb[4];
                ldm4t(vb, vsb + (vrow * SM_STRIDE + dcp * 16 + vcb) * 2);
                mma16816(Of[2*dcp],     P[jc][0], P[jc][1], P[jc][2], P[jc][3], vb[0], vb[1]);
                mma16816(Of[2*dcp + 1], P[jc][0], P[jc][1], P[jc][2], P[jc][3], vb[2], vb[3]);
            }
        }

        if (it + 1 < 64) {
            asm volatile("cp.async.wait_group 0;\n");
            __syncthreads();
        }
    }

    float inv0 = 1.0f / lrow0, inv1 = 1.0f / lrow1;
    int m = m0 + (w << 4) + gid;
    #pragma unroll
    for (int dc = 0; dc < 8; dc++) {
        int d0 = dc * 8 + tig * 2;
        g_O[(b * 64 + d0)     * NDS + m]     = Of[dc][0] * inv0;
        g_O[(b * 64 + d0 + 1) * NDS + m]     = Of[dc][1] * inv0;
        g_O[(b * 64 + d0)     * NDS + m + 8] = Of[dc][2] * inv1;
        g_O[(b * 64 + d0 + 1) * NDS + m + 8] = Of[dc][3] * inv1;
    }
}

// ============================================================================
// K4: convout — ROUND 7: cp.async f32 staging ring (depth 2) + hi-only
// activations (2-pass: Wh@Ah + Wl@Ah) + fused epilogue.
// ============================================================================
#define CO_OFF_WH  0
#define CO_OFF_WL  25600
#define CO_OFF_STG 51200
#define CO_STG_BUF 16384                 // 16 rows x 256 f32
#define CO_OFF_ACT 83968
#define CO_ACT_BUF 8448                  // [16][264] f16
#define CONVOUT_SMEM (83968 + 2 * 8448)  // 100864

__device__ __forceinline__ void co_issue_stage(
    const float* __restrict__ x1, const float* __restrict__ x2,
    int b, int p0, int t, unsigned dstbase, int ks)
{
    #pragma unroll
    for (int rep = 0; rep < 4; rep++) {
        int i = t + rep * 256;           // 0..1023 (16B units)
        int row = i >> 6, off = i & 63;
        int c = ks * 16 + row;
        const float* src = (c < 128) ? x1 + (size_t)(b * 128 + c) * HW
                                     : x2 + (size_t)(b * 64 + c - 128) * HW;
        cpasync16(dstbase + row * 1024 + off * 16, src + p0 + off * 4);
    }
    asm volatile("cp.async.commit_group;\n");
}

__device__ __forceinline__ void co_convert(const float* stg, __half* AH, int t)
{
    #pragma unroll
    for (int ch = 0; ch < 4; ch++) {
        int i = ch * 1024 + t * 4;
        int row = i >> 8, col = i & 255;
        float4 v = *(const float4*)(stg + i);
        __half2 h0 = __floats2half2_rn(v.x, v.y);
        __half2 h1 = __floats2half2_rn(v.z, v.w);
        uint2 u;
        u.x = *(unsigned*)&h0;
        u.y = *(unsigned*)&h1;
        *(uint2*)&AH[row * 264 + col] = u;
    }
}

__global__ __launch_bounds__(256, 2) void convout_kernel(
    const float* __restrict__ x1, const float* __restrict__ x2,
    const float* __restrict__ w,  const float* __restrict__ bias,
    const float* __restrict__ gamma, float* __restrict__ out)
{
    extern __shared__ char smc[];
    __half* WH = (__half*)(smc + CO_OFF_WH);
    __half* WL = (__half*)(smc + CO_OFF_WL);
    unsigned smu = (unsigned)__cvta_generic_to_shared(smc);

    int t = threadIdx.x;
    int lane = t & 31, wp = t >> 5;
    int ln15 = lane & 15, hb8 = (lane >> 4) * 8;
    int y = blockIdx.x, b = blockIdx.y;
    int p0 = y << 8;
    int ndbase = (y >> 2) << 6;

    // prefetch stages 0,1 immediately (before weight conversion) for overlap
    co_issue_stage(x1, x2, b, p0, t, smu + CO_OFF_STG, 0);
    co_issue_stage(x1, x2, b, p0, t, smu + CO_OFF_STG + CO_STG_BUF, 1);

    for (int i = t; i < 12288; i += 256) {
        int o = i / 192, c = i - o * 192;
        float v = w[i];
        __half h = __float2half_rn(v);
        WH[o * 200 + c] = h;
        WL[o * 200 + c] = __float2half_rn(v - __half2float(h));
    }

    asm volatile("cp.async.wait_group 1;\n");  // stage 0 landed
    __syncthreads();
    co_convert((const float*)(smc + CO_OFF_STG), (__half*)(smc + CO_OFF_ACT), t);

    float acc[4][4][4];
    #pragma unroll
    for (int mt = 0; mt < 4; mt++)
        #pragma unroll
        for (int nb = 0; nb < 4; nb++)
            #pragma unroll
            for (int q = 0; q < 4; q++) acc[mt][nb][q] = 0.0f;

    unsigned whB = smu + CO_OFF_WH + (ln15 * 200 + hb8) * 2;
    unsigned wlB = smu + CO_OFF_WL + (ln15 * 200 + hb8) * 2;

    #pragma unroll 1
    for (int ks = 0; ks < 12; ks++) {
        __syncthreads();   // actbuf[ks&1] visible; ring[ks&1] reads complete
        if (ks + 2 < 12)
            co_issue_stage(x1, x2, b, p0, t,
                           smu + CO_OFF_STG + (ks & 1) * CO_STG_BUF, ks + 2);

        unsigned actH = smu + CO_OFF_ACT + (ks & 1) * CO_ACT_BUF +
                        (ln15 * 264 + wp * 32 + hb8) * 2;
        unsigned Bh[8], A[4][4];
        ldm4t(Bh,     actH);
        ldm4t(Bh + 4, actH + 32);
        #pragma unroll
        for (int mt = 0; mt < 4; mt++)
            ldm4(A[mt], whB + mt * 6400 + ks * 32);
        #pragma unroll
        for (int mt = 0; mt < 4; mt++) {
            mma16816(acc[mt][0], A[mt][0], A[mt][1], A[mt][2], A[mt][3], Bh[0], Bh[1]);
            mma16816(acc[mt][1], A[mt][0], A[mt][1], A[mt][2], A[mt][3], Bh[2], Bh[3]);
            mma16816(acc[mt][2], A[mt][0], A[mt][1], A[mt][2], A[mt][3], Bh[4], Bh[5]);
            mma16816(acc[mt][3], A[mt][0], A[mt][1], A[mt][2], A[mt][3], Bh[6], Bh[7]);
        }
        #pragma unroll
        for (int mt = 0; mt < 4; mt++)
            ldm4(A[mt], wlB + mt * 6400 + ks * 32);
        #pragma unroll
        for (int mt = 0; mt < 4; mt++) {
            mma16816(acc[mt][0], A[mt][0], A[mt][1], A[mt][2], A[mt][3], Bh[0], Bh[1]);
            mma16816(acc[mt][1], A[mt][0], A[mt][1], A[mt][2], A[mt][3], Bh[2], Bh[3]);
            mma16816(acc[mt][2], A[mt][0], A[mt][1], A[mt][2], A[mt][3], Bh[4], Bh[5]);
            mma16816(acc[mt][3], A[mt][0], A[mt][1], A[mt][2], A[mt][3], Bh[6], Bh[7]);
        }

        if (ks + 1 < 12) {
            if (ks + 2 < 12) { asm volatile("cp.async.wait_group 1;\n"); }
            else             { asm volatile("cp.async.wait_group 0;\n"); }
            co_convert((const float*)(smc + CO_OFF_STG + ((ks + 1) & 1) * CO_STG_BUF),
                       (__half*)(smc + CO_OFF_ACT + ((ks + 1) & 1) * CO_ACT_BUF), t);
        }
    }

    // epilogue: prefetch O/ef tiles to regs, overlay OS/ES on staging smem
    float ov[16], evv[16];
    {
        int o = t >> 2, c0 = (t & 3) << 4;
        const float* po = g_O   + (size_t)(b * 64 + o) * NDS + ndbase + c0;
        const float* pe = g_efd + (size_t)(b * 64 + o) * NDS + ndbase + c0;
        #pragma unroll
        for (int j = 0; j < 4; j++) {
            *(float4*)&ov[4*j]  = *(const float4*)(po + 4*j);
            *(float4*)&evv[4*j] = *(const float4*)(pe + 4*j);
        }
    }
    __syncthreads();

    float* OS = (float*)(smc + CO_OFF_STG);
    float* ES = OS + 64 * 68;
    {
        int o = t >> 2, c0 = (t & 3) << 4;
        #pragma unroll
        for (int j = 0; j < 4; j++) {
            *(float4*)&OS[o * 68 + c0 + 4*j] = *(const float4*)&ov[4*j];
            *(float4*)&ES[o * 68 + c0 + 4*j] = *(const float4*)&evv[4*j];
        }
    }
    __syncthreads();

    float tg = THITA_F * __ldg(gamma);
    int g = lane >> 2, tig = lane & 3;
    #pragma unroll
    for (int mt = 0; mt < 4; mt++) {
        int o = mt * 16 + g;
        float bb0 = __ldg(&bias[o]), bb1 = __ldg(&bias[o + 8]);
        #pragma unroll
        for (int nb = 0; nb < 4; nb++) {
            int px = wp * 32 + nb * 8 + tig * 2;
            int ndc = px >> 2;
            float a0 = tg * OS[o * 68 + ndc];
            float a1 = tg * OS[(o + 8) * 68 + ndc];
            float2 r0 = make_float2(fmaxf(acc[mt][nb][0] + bb0, 0.0f) + a0,
                                    fmaxf(acc[mt][nb][1] + bb0, 0.0f) + a0);
            float2 r1 = make_float2(fmaxf(acc[mt][nb][2] + bb1, 0.0f) + a1,
                                    fmaxf(acc[mt][nb][3] + bb1, 0.0f) + a1);
            *(float2*)(out + (size_t)(b * 64 + o)     * HW + p0 + px) = r0;
            *(float2*)(out + (size_t)(b * 64 + o + 8) * HW + p0 + px) = r1;
        }
    }

    int xq = t & 63;
    #pragma unroll
    for (int rep = 0; rep < 16; rep++) {
        int o = rep * 4 + (t >> 6);
        float v = ES[o * 68 + xq];
        *(float4*)(out + OUT2OFF + (size_t)(b * 64 + o) * HW + p0 + (xq << 2)) =
            make_float4(v, v, v, v);
    }
}

// ============================================================================
extern "C" void kernel_launch(void* const* d_in, const int* in_sizes, int n_in,
                              void* d_out, int out_size)
{
    const float* x1    = (const float*)d_in[0];
    const float* x2    = (const float*)d_in[1];
    const float* ev    = (const float*)d_in[2];
    const float* xw0   = (const float*)d_in[3];
    const float* xb0   = (const float*)d_in[4];
    const float* xw1   = (const float*)d_in[5];
    const float* xb1   = (const float*)d_in[6];
    const float* ew0   = (const float*)d_in[7];
    const float* eb0   = (const float*)d_in[8];
    const float* ew1   = (const float*)d_in[9];
    const float* eb1   = (const float*)d_in[10];
    const float* qw    = (const float*)d_in[11];
    const float* qb    = (const float*)d_in[12];
    const float* kw    = (const float*)d_in[13];
    const float* kb    = (const float*)d_in[14];
    const float* vw    = (const float*)d_in[15];
    const float* vb    = (const float*)d_in[16];
    const float* gamma = (const float*)d_in[17];
    float* out = (float*)d_out;

    cudaFuncSetAttribute(prep_kernel,
                         cudaFuncAttributeMaxDynamicSharedMemorySize, PREP_SMEM);
    cudaFuncSetAttribute(qkv_kernel,
                         cudaFuncAttributeMaxDynamicSharedMemorySize, QKV_SMEM);
    cudaFuncSetAttribute(attn_kernel,
                         cudaFuncAttributeMaxDynamicSharedMemorySize, ATTN_SMEM);
    cudaFuncSetAttribute(convout_kernel,
                         cudaFuncAttributeMaxDynamicSharedMemorySize, CONVOUT_SMEM);

    prep_kernel<<<dim3(NDS / 64, BATCH, 2), 128, PREP_SMEM>>>(
        x1, x2, ev, xw0, xb0, ew0, eb0, ew1, eb1);
    qkv_kernel<<<dim3(NDS / 64, BATCH), 128, QKV_SMEM>>>(
        xw1, xb1, qw, qb, kw, kb, vw, vb);
    attn_kernel<<<dim3(NDS / 128, BATCH), 256, ATTN_SMEM>>>();
    convout_kernel<<<dim3(256, BATCH), 256, CONVOUT_SMEM>>>(
        x1, x2, xw0, xb0, gamma, out);
}

// round 8
// speedup vs baseline: 1.4238x; 1.0650x over previous
#include <cuda_runtime.h>
#include <cuda_fp16.h>
#include <math.h>

#define BATCH 4
#define CHN 64
#define HW 65536        // 256*256
#define NDS 4096        // 64*64 downsampled pixels
#define THITA_F 1.0e-4f
#define OUT2OFF (BATCH * CHN * HW)

// ---------------- scratch (device globals) ----------------------------------
__device__ __half g_xdsh[BATCH * CHN * NDS];    // down4(x) f16 [b][c][n]
__device__ float  g_efd [BATCH * CHN * NDS];    // ef ds fp32 [b][c][n] (feeds ef_up)
__device__ __half g_efdh[BATCH * CHN * NDS];    // ef ds f16 [b][c][n] (feeds k conv)
__device__ __half g_qh[BATCH * NDS * CHN];      // [b][n][d] f16
__device__ __half g_kh[BATCH * NDS * CHN];
__device__ __half g_vh[BATCH * NDS * CHN];
__device__ float  g_O[BATCH * CHN * NDS];       // attention output [b][d][m]
__device__ __half g_wh[64 * 200];               // conv0 weights f16 hi [o][c pad 200]
__device__ __half g_wl[64 * 200];               // conv0 weights f16 lo

// ============================================================================
// mma / ldmatrix helpers
// ============================================================================
__device__ __forceinline__ void mma16816(float* d,
    unsigned a0, unsigned a1, unsigned a2, unsigned a3,
    unsigned b0, unsigned b1)
{
    asm volatile(
        "mma.sync.aligned.m16n8k16.row.col.f32.f16.f16.f32 "
        "{%0,%1,%2,%3}, {%4,%5,%6,%7}, {%8,%9}, {%0,%1,%2,%3};\n"
        : "+f"(d[0]), "+f"(d[1]), "+f"(d[2]), "+f"(d[3])
        : "r"(a0), "r"(a1), "r"(a2), "r"(a3), "r"(b0), "r"(b1));
}
__device__ __forceinline__ void ldm4(unsigned* r, unsigned a) {
    asm volatile("ldmatrix.sync.aligned.m8n8.x4.shared.b16 {%0,%1,%2,%3}, [%4];\n"
        : "=r"(r[0]), "=r"(r[1]), "=r"(r[2]), "=r"(r[3]) : "r"(a));
}
__device__ __forceinline__ void ldm4t(unsigned* r, unsigned a) {
    asm volatile("ldmatrix.sync.aligned.m8n8.x4.trans.shared.b16 {%0,%1,%2,%3}, [%4];\n"
        : "=r"(r[0]), "=r"(r[1]), "=r"(r[2]), "=r"(r[3]) : "r"(a));
}
__device__ __forceinline__ void cpasync16(unsigned dst, const void* src) {
    asm volatile("cp.async.cg.shared.global [%0], [%1], 16;\n"
        :: "r"(dst), "l"(src));
}
__device__ __forceinline__ unsigned hpack(__half a, __half b) {
    __half2 h = __halves2half2(a, b);
    return *(unsigned*)&h;
}
__device__ __forceinline__ unsigned packh2(float a, float b) {
    __half2 h = __floats2half2_rn(a, b);
    return *(unsigned*)&h;
}
__device__ __forceinline__ float sexp(float s, float c) {
    float t = fmaf(s, 12102203.16f, c);
    t = fmaxf(t, 0.0f);
    return __int_as_float(__float2int_rn(t));
}

// single-pass f16 GEMM: acc[8][4] += W(16 rows at wb) @ act(K=16*nks x 64, stride 72)
__device__ __forceinline__ void gemm1p(float acc[8][4], unsigned wb, int wstride,
                                       unsigned ab, int nks, int lane)
{
    int ln15 = lane & 15, hb8 = (lane >> 4) * 8;
    unsigned wl = wb + (ln15 * wstride + hb8) * 2;
    #pragma unroll
    for (int ks = 0; ks < nks; ks++) {
        unsigned al = ab + ((ks * 16 + ln15) * 72 + hb8) * 2;
        unsigned B[16], A[4];
        ldm4t(B,      al);
        ldm4t(B + 4,  al + 32);
        ldm4t(B + 8,  al + 64);
        ldm4t(B + 12, al + 96);
        ldm4(A, wl + ks * 32);
        #pragma unroll
        for (int nc = 0; nc < 8; nc++) {
            int ib = (nc >> 1) * 4 + (nc & 1) * 2;
            mma16816(acc[nc], A[0], A[1], A[2], A[3], B[ib], B[ib + 1]);
        }
    }
}

// 3-pass hi/lo GEMM (K=64): acc += Wh@Ah + Wh@Al + Wl@Ah
__device__ __forceinline__ void gemm3p(float acc[8][4],
    unsigned wh, unsigned wlo, unsigned ah, unsigned alo, int lane)
{
    int ln15 = lane & 15, hb8 = (lane >> 4) * 8;
    unsigned wbh = wh  + (ln15 * 72 + hb8) * 2;
    unsigned wbl = wlo + (ln15 * 72 + hb8) * 2;
    #pragma unroll
    for (int ks = 0; ks < 4; ks++) {
        unsigned abh = ah  + ((ks * 16 + ln15) * 72 + hb8) * 2;
        unsigned abl = alo + ((ks * 16 + ln15) * 72 + hb8) * 2;
        unsigned Bh[16], Bl[16], Wf[4], Lf[4];
        ldm4t(Bh,      abh);
        ldm4t(Bh + 4,  abh + 32);
        ldm4t(Bh + 8,  abh + 64);
        ldm4t(Bh + 12, abh + 96);
        ldm4t(Bl,      abl);
        ldm4t(Bl + 4,  abl + 32);
        ldm4t(Bl + 8,  abl + 64);
        ldm4t(Bl + 12, abl + 96);
        ldm4(Wf, wbh + ks * 32);
        ldm4(Lf, wbl + ks * 32);
        #pragma unroll
        for (int nc = 0; nc < 8; nc++) {
            int ib = (nc >> 1) * 4 + (nc & 1) * 2;
            mma16816(acc[nc], Wf[0], Wf[1], Wf[2], Wf[3], Bh[ib], Bh[ib + 1]);
            mma16816(acc[nc], Wf[0], Wf[1], Wf[2], Wf[3], Bl[ib], Bl[ib + 1]);
            mma16816(acc[nc], Lf[0], Lf[1], Lf[2], Lf[3], Bh[ib], Bh[ib + 1]);
        }
    }
}

// ============================================================================
// K0: wconv — one-time conv0 weight split to f16 hi/lo globals
// ============================================================================
__global__ void wconv_kernel(const float* __restrict__ w)
{
    int i = blockIdx.x * 256 + threadIdx.x;
    if (i < 12288) {
        int o = i / 192, c = i - o * 192;
        float v = w[i];
        __half h = __float2half_rn(v);
        g_wh[o * 200 + c] = h;
        g_wl[o * 200 + c] = __float2half_rn(v - __half2float(h));
    }
}

// ============================================================================
// K1: prep — z=0: conv0_ds (f16 1-pass) -> g_xdsh; z=1: ef chain (3-pass)
// ============================================================================
#define PREP_SMEM (64 * 200 * 2 + 192 * 72 * 2)   // 53248

__global__ __launch_bounds__(128) void prep_kernel(
    const float* __restrict__ x1, const float* __restrict__ x2,
    const float* __restrict__ ev,
    const float* __restrict__ xw0, const float* __restrict__ xb0,
    const float* __restrict__ ew0, const float* __restrict__ eb0,
    const float* __restrict__ ew1, const float* __restrict__ eb1)
{
    extern __shared__ char smc[];
    unsigned smu = (unsigned)__cvta_generic_to_shared(smc);
    int t = threadIdx.x, lane = t & 31, w = t >> 5;
    int gid = lane >> 2, tig = lane & 3;
    int blk = blockIdx.x, b = blockIdx.y;
    int n0 = blk << 6;

    float acc[8][4];
    #pragma unroll
    for (int nc = 0; nc < 8; nc++)
        #pragma unroll
        for (int q = 0; q < 4; q++) acc[nc][q] = 0.0f;

    if (blockIdx.z == 0) {
        __half* W  = (__half*)smc;
        __half* Ac = (__half*)(smc + 64 * 200 * 2);
        for (int i = t; i < 12288; i += 128) {
            int o = i / 192, c = i - o * 192;
            W[o * 200 + c] = __float2half_rn(xw0[i]);
        }
        for (int i = t; i < 12288; i += 128) {
            int c = i >> 6, x = i & 63;
            const float* s = (c < 128) ? x1 + (size_t)(b * 128 + c) * HW
                                       : x2 + (size_t)(b * 64 + c - 128) * HW;
            Ac[c * 72 + x] = __float2half_rn(s[(blk << 10) + (x << 2)]);
        }
        __syncthreads();

        gemm1p(acc, smu + (w * 16) * 200 * 2, 200,
               smu + 64 * 200 * 2, 12, lane);

        int o = (w << 4) + gid;
        float b0 = __ldg(&xb0[o]), b1 = __ldg(&xb0[o + 8]);
        #pragma unroll
        for (int nc = 0; nc < 8; nc++) {
            int n = n0 + nc * 8 + tig * 2;
            *(__half2*)&g_xdsh[(size_t)(b * 64 + o) * NDS + n] =
                __floats2half2_rn(fmaxf(acc[nc][0] + b0, 0.0f),
                                  fmaxf(acc[nc][1] + b0, 0.0f));
            *(__half2*)&g_xdsh[(size_t)(b * 64 + o + 8) * NDS + n] =
                __floats2half2_rn(fmaxf(acc[nc][2] + b1, 0.0f),
                                  fmaxf(acc[nc][3] + b1, 0.0f));
        }
    } else {
        __half* Wh = (__half*)smc;
        __half* Wl = Wh + 64 * 72;
        __half* Ah = Wl + 64 * 72;
        __half* Al = Ah + 64 * 72;
        unsigned oWh = smu, oWl = smu + 9216, oAh = smu + 18432, oAl = smu + 27648;

        for (int i = t; i < 4096; i += 128) {
            float v = ew0[i];
            __half h = __float2half_rn(v);
            int o = i >> 6, c = i & 63;
            Wh[o * 72 + c] = h;
            Wl[o * 72 + c] = __float2half_rn(v - __half2float(h));
        }
        for (int i = t; i < 4096; i += 128) {
            int c = i >> 6, x = i & 63;
            float v = ev[(size_t)(b * 64 + c) * HW + (blk << 10) + (x << 2)];
            __half h = __float2half_rn(v);
            Ah[c * 72 + x] = h;
            Al[c * 72 + x] = __float2half_rn(v - __half2float(h));
        }
        __syncthreads();

        gemm3p(acc, oWh + (w * 16) * 144, oWl + (w * 16) * 144, oAh, oAl, lane);
        __syncthreads();

        {
            int o = (w << 4) + gid;
            float b0 = __ldg(&eb0[o]), b1 = __ldg(&eb0[o + 8]);
            #pragma unroll
            for (int nc = 0; nc < 8; nc++) {
                int px = nc * 8 + tig * 2;
                float t0 = fmaxf(acc[nc][0] + b0, 0.0f);
                float t1 = fmaxf(acc[nc][1] + b0, 0.0f);
                float t2 = fmaxf(acc[nc][2] + b1, 0.0f);
                float t3 = fmaxf(acc[nc][3] + b1, 0.0f);
                __half h0 = __float2half_rn(t0), h1 = __float2half_rn(t1);
                __half h2 = __float2half_rn(t2), h3 = __float2half_rn(t3);
                *(__half2*)&Ah[o * 72 + px] = __halves2half2(h0, h1);
                *(__half2*)&Al[o * 72 + px] = __floats2half2_rn(
                    t0 - __half2float(h0), t1 - __half2float(h1));
                *(__half2*)&Ah[(o + 8) * 72 + px] = __halves2half2(h2, h3);
                *(__half2*)&Al[(o + 8) * 72 + px] = __floats2half2_rn(
                    t2 - __half2float(h2), t3 - __half2float(h3));
            }
        }
        for (int i = t; i < 4096; i += 128) {
            float v = ew1[i];
            __half h = __float2half_rn(v);
            int o = i >> 6, c = i & 63;
            Wh[o * 72 + c] = h;
            Wl[o * 72 + c] = __float2half_rn(v - __half2float(h));
        }
        __syncthreads();

        #pragma unroll
        for (int nc = 0; nc < 8; nc++)
            #pragma unroll
            for (int q = 0; q < 4; q++) acc[nc][q] = 0.0f;
        gemm3p(acc, oWh + (w * 16) * 144, oWl + (w * 16) * 144, oAh, oAl, lane);

        int o = (w << 4) + gid;
        float b0 = __ldg(&eb1[o]), b1 = __ldg(&eb1[o + 8]);
        #pragma unroll
        for (int nc = 0; nc < 8; nc++) {
            int n = n0 + nc * 8 + tig * 2;
            float r0 = fmaxf(acc[nc][0] + b0, 0.0f);
            float r1 = fmaxf(acc[nc][1] + b0, 0.0f);
            float r2 = fmaxf(acc[nc][2] + b1, 0.0f);
            float r3 = fmaxf(acc[nc][3] + b1, 0.0f);
            *(float2*)&g_efd[(size_t)(b * 64 + o) * NDS + n]     = make_float2(r0, r1);
            *(float2*)&g_efd[(size_t)(b * 64 + o + 8) * NDS + n] = make_float2(r2, r3);
            *(__half2*)&g_efdh[(size_t)(b * 64 + o) * NDS + n]     = __floats2half2_rn(r0, r1);
            *(__half2*)&g_efdh[(size_t)(b * 64 + o + 8) * NDS + n] = __floats2half2_rn(r2, r3);
        }
    }
}

// ============================================================================
// K2: qkv — all f16 1-pass mma (unchanged)
// ============================================================================
#define QKV_SMEM (4 * 64 * 72 * 2)

__global__ __launch_bounds__(128) void qkv_kernel(
    const float* __restrict__ xw1, const float* __restrict__ xb1,
    const float* __restrict__ qw,  const float* __restrict__ qb,
    const float* __restrict__ kw,  const float* __restrict__ kb,
    const float* __restrict__ vw,  const float* __restrict__ vb)
{
    extern __shared__ char smc[];
    unsigned smu = (unsigned)__cvta_generic_to_shared(smc);
    __half* W   = (__half*)smc;
    __half* Act = W + 64 * 72;
    __half* Tb  = Act + 64 * 72;
    __half* Tr  = Tb + 64 * 72;
    unsigned oW = smu, oAct = smu + 9216, oTb = smu + 18432;

    int t = threadIdx.x, lane = t & 31, w = t >> 5;
    int gid = lane >> 2, tig = lane & 3;
    int blk = blockIdx.x, b = blockIdx.y;
    int n0 = blk << 6;
    int o = (w << 4) + gid;

    for (int i = t; i < 512; i += 128) {
        int row = i >> 3, off = i & 7;
        *(uint4*)&Act[row * 72 + off * 8] =
            *(const uint4*)&g_xdsh[(size_t)(b * 64 + row) * NDS + n0 + off * 8];
    }
    for (int i = t; i < 4096; i += 128)
        W[(i >> 6) * 72 + (i & 63)] = __float2half_rn(xw1[i]);
    __syncthreads();

    float acc[8][4];
    #pragma unroll
    for (int nc = 0; nc < 8; nc++)
        #pragma unroll
        for (int q = 0; q < 4; q++) acc[nc][q] = 0.0f;
    gemm1p(acc, oW + (w * 16) * 144, 72, oAct, 4, lane);
    {
        float b0 = __ldg(&xb1[o]), b1 = __ldg(&xb1[o + 8]);
        #pragma unroll
        for (int nc = 0; nc < 8; nc++) {
            int px = nc * 8 + tig * 2;
            *(__half2*)&Tb[o * 72 + px] = __floats2half2_rn(
                fmaxf(acc[nc][0] + b0, 0.0f), fmaxf(acc[nc][1] + b0, 0.0f));
            *(__half2*)&Tb[(o + 8) * 72 + px] = __floats2half2_rn(
                fmaxf(acc[nc][2] + b1, 0.0f), fmaxf(acc[nc][3] + b1, 0.0f));
        }
    }
    __syncthreads();
    for (int i = t; i < 4096; i += 128)
        W[(i >> 6) * 72 + (i & 63)] = __float2half_rn(qw[i]);
    __syncthreads();

    #pragma unroll
    for (int nc = 0; nc < 8; nc++)
        #pragma unroll
        for (int q = 0; q < 4; q++) acc[nc][q] = 0.0f;
    gemm1p(acc, oW + (w * 16) * 144, 72, oTb, 4, lane);
    {
        float b0 = __ldg(&qb[o]), b1 = __ldg(&qb[o + 8]);
        #pragma unroll
        for (int nc = 0; nc < 8; nc++) {
            int px = nc * 8 + tig * 2;
            Tr[px * 72 + o]           = __float2half_rn(fmaxf(acc[nc][0] + b0, 0.0f));
            Tr[(px + 1) * 72 + o]     = __float2half_rn(fmaxf(acc[nc][1] + b0, 0.0f));
            Tr[px * 72 + o + 8]       = __float2half_rn(fmaxf(acc[nc][2] + b1, 0.0f));
            Tr[(px + 1) * 72 + o + 8] = __float2half_rn(fmaxf(acc[nc][3] + b1, 0.0f));
        }
    }
    __syncthreads();
    for (int i = t; i < 512; i += 128) {
        int row = i >> 3, off = i & 7;
        *(uint4*)&g_qh[((size_t)b * NDS + n0 + row) * 64 + off * 8] =
            *(uint4*)&Tr[row * 72 + off * 8];
    }
    for (int i = t; i < 4096; i += 128)
        W[(i >> 6) * 72 + (i & 63)] = __float2half_rn(vw[i]);
    __syncthreads();

    #pragma unroll
    for (int nc = 0; nc < 8; nc++)
        #pragma unroll
        for (int q = 0; q < 4; q++) acc[nc][q] = 0.0f;
    gemm1p(acc, oW + (w * 16) * 144, 72, oTb, 4, lane);
    {
        float b0 = __ldg(&vb[o]), b1 = __ldg(&vb[o + 8]);
        #pragma unroll
        for (int nc = 0; nc < 8; nc++) {
            int px = nc * 8 + tig * 2;
            Tr[px * 72 + o]           = __float2half_rn(fmaxf(acc[nc][0] + b0, 0.0f));
            Tr[(px + 1) * 72 + o]     = __float2half_rn(fmaxf(acc[nc][1] + b0, 0.0f));
            Tr[px * 72 + o + 8]       = __float2half_rn(fmaxf(acc[nc][2] + b1, 0.0f));
            Tr[(px + 1) * 72 + o + 8] = __float2half_rn(fmaxf(acc[nc][3] + b1, 0.0f));
        }
    }
    __syncthreads();
    for (int i = t; i < 512; i += 128) {
        int row = i >> 3, off = i & 7;
        *(uint4*)&g_vh[((size_t)b * NDS + n0 + row) * 64 + off * 8] =
            *(uint4*)&Tr[row * 72 + off * 8];
    }
    for (int i = t; i < 4096; i += 128)
        W[(i >> 6) * 72 + (i & 63)] = __float2half_rn(kw[i]);
    for (int i = t; i < 512; i += 128) {
        int row = i >> 3, off = i & 7;
        *(uint4*)&Act[row * 72 + off * 8] =
            *(const uint4*)&g_efdh[(size_t)(b * 64 + row) * NDS + n0 + off * 8];
    }
    __syncthreads();

    #pragma unroll
    for (int nc = 0; nc < 8; nc++)
        #pragma unroll
        for (int q = 0; q < 4; q++) acc[nc][q] = 0.0f;
    gemm1p(acc, oW + (w * 16) * 144, 72, oAct, 4, lane);
    {
        float b0 = __ldg(&kb[o]), b1 = __ldg(&kb[o + 8]);
        #pragma unroll
        for (int nc = 0; nc < 8; nc++) {
            int px = nc * 8 + tig * 2;
            Tr[px * 72 + o]           = __float2half_rn(fmaxf(acc[nc][0] + b0, 0.0f));
            Tr[(px + 1) * 72 + o]     = __float2half_rn(fmaxf(acc[nc][1] + b0, 0.0f));
            Tr[px * 72 + o + 8]       = __float2half_rn(fmaxf(acc[nc][2] + b1, 0.0f));
            Tr[(px + 1) * 72 + o + 8] = __float2half_rn(fmaxf(acc[nc][3] + b1, 0.0f));
        }
    }
    __syncthreads();
    for (int i = t; i < 512; i += 128) {
        int row = i >> 3, off = i & 7;
        *(uint4*)&g_kh[((size_t)b * NDS + n0 + row) * 64 + off * 8] =
            *(uint4*)&Tr[row * 72 + off * 8];
    }
}

// ============================================================================
// K3: flash attention — R3 config + PDL trigger so convout can overlap
// ============================================================================
#define SM_STRIDE 72
#define ATTN_SMEM ((128 * SM_STRIDE + 4 * 64 * SM_STRIDE) * 2)

__global__ __launch_bounds__(256, 1) void attn_kernel()
{
    extern __shared__ __half smh[];
    __half* qs  = smh;
    __half* ks0 = smh + 128 * SM_STRIDE;
    __half* vs0 = ks0 + 2 * 64 * SM_STRIDE;

    int tid  = threadIdx.x;
    int lane = tid & 31, w = tid >> 5;
    int gid  = lane >> 2, tig = lane & 3;
    int b    = blockIdx.y;
    int m0   = blockIdx.x << 7;

    const __half* qg = g_qh + (size_t)b * NDS * 64;
    const __half* kg = g_kh + (size_t)b * NDS * 64;
    const __half* vg = g_vh + (size_t)b * NDS * 64;

    unsigned qs_base = (unsigned)__cvta_generic_to_shared(qs);
    unsigned ks_base = (unsigned)__cvta_generic_to_shared(ks0);
    unsigned vs_base = (unsigned)__cvta_generic_to_shared(vs0);

    #pragma unroll
    for (int rep = 0; rep < 2; rep++) {
        int c = tid + rep * 256;
        int row = c >> 3, off = c & 7;
        cpasync16(ks_base + (row * SM_STRIDE + off * 8) * 2, kg + row * 64 + off * 8);
        cpasync16(vs_base + (row * SM_STRIDE + off * 8) * 2, vg + row * 64 + off * 8);
    }
    asm volatile("cp.async.commit_group;\n");

    // PDL: allow the dependent convout grid to start launching now
    asm volatile("griddepcontrol.launch_dependents;" ::: "memory");

    for (int c = tid; c < 1024; c += 256) {
        int row = c >> 3, off = c & 7;
        *(uint4*)(qs + row * SM_STRIDE + off * 8) =
            *(const uint4*)(qg + (size_t)(m0 + row) * 64 + off * 8);
    }
    asm volatile("cp.async.wait_group 0;\n");
    __syncthreads();

    unsigned qa[4][4];
    {
        int row = (w << 4) + (lane & 15);
        #pragma unroll
        for (int kc = 0; kc < 4; kc++) {
            int dof = kc * 16 + (lane >> 4) * 8;
            ldm4(qa[kc], qs_base + (row * SM_STRIDE + dof) * 2);
        }
    }

    float Of[8][4];
    #pragma unroll
    for (int dc = 0; dc < 8; dc++)
        #pragma unroll
        for (int q = 0; q < 4; q++) Of[dc][q] = 0.0f;
    float mrow0 = -1e30f, mrow1 = -1e30f, lrow0 = 0.0f, lrow1 = 0.0f;
    const unsigned ONES = 0x3C003C00u;

    for (int it = 0; it < 64; it++) {
        int bf = it & 1;
        unsigned ksb = ks_base + bf * 64 * SM_STRIDE * 2;
        unsigned vsb = vs_base + bf * 64 * SM_STRIDE * 2;

        if (it + 1 < 64) {
            int n0n = (it + 1) << 6;
            int nb  = (it + 1) & 1;
            #pragma unroll
            for (int rep = 0; rep < 2; rep++) {
                int c = tid + rep * 256;
                int row = c >> 3, off = c & 7;
                cpasync16(ks_base + (nb * 64 * SM_STRIDE + row * SM_STRIDE + off * 8) * 2,
                          kg + (size_t)(n0n + row) * 64 + off * 8);
                cpasync16(vs_base + (nb * 64 * SM_STRIDE + row * SM_STRIDE + off * 8) * 2,
                          vg + (size_t)(n0n + row) * 64 + off * 8);
            }
            asm volatile("cp.async.commit_group;\n");
        }

        float S[8][4];
        #pragma unroll
        for (int nc = 0; nc < 8; nc++) {
            unsigned kb[8];
            int krow = nc * 8 + (lane & 7);
            int kd   = (lane >> 3) * 8;
            ldm4(kb,     ksb + (krow * SM_STRIDE + kd) * 2);
            ldm4(kb + 4, ksb + (krow * SM_STRIDE + 32 + kd) * 2);
            #pragma unroll
            for (int q = 0; q < 4; q++) S[nc][q] = 0.0f;
            mma16816(S[nc], qa[0][0], qa[0][1], qa[0][2], qa[0][3], kb[0], kb[1]);
            mma16816(S[nc], qa[1][0], qa[1][1], qa[1][2], qa[1][3], kb[2], kb[3]);
            mma16816(S[nc], qa[2][0], qa[2][1], qa[2][2], qa[2][3], kb[4], kb[5]);
            mma16816(S[nc], qa[3][0], qa[3][1], qa[3][2], qa[3][3], kb[6], kb[7]);
        }

        float tm0 = fmaxf(S[0][0], S[0][1]);
        float tm1 = fmaxf(S[0][2], S[0][3]);
        #pragma unroll
        for (int nc = 1; nc < 8; nc++) {
            tm0 = fmaxf(tm0, fmaxf(S[nc][0], S[nc][1]));
            tm1 = fmaxf(tm1, fmaxf(S[nc][2], S[nc][3]));
        }
        tm0 = fmaxf(tm0, __shfl_xor_sync(0xffffffffu, tm0, 1));
        tm0 = fmaxf(tm0, __shfl_xor_sync(0xffffffffu, tm0, 2));
        tm1 = fmaxf(tm1, __shfl_xor_sync(0xffffffffu, tm1, 1));
        tm1 = fmaxf(tm1, __shfl_xor_sync(0xffffffffu, tm1, 2));
        float nm0 = fmaxf(mrow0, tm0), nm1 = fmaxf(mrow1, tm1);
        float sc0 = exp2f((mrow0 - nm0) * 1.44269504f);
        float sc1 = exp2f((mrow1 - nm1) * 1.44269504f);
        mrow0 = nm0; mrow1 = nm1;
        float c0 = 1064866805.0f - nm0 * 12102203.16f;
        float c1 = 1064866805.0f - nm1 * 12102203.16f;

        unsigned P[4][4];
        #pragma unroll
        for (int jc = 0; jc < 4; jc++) {
            P[jc][0] = packh2(sexp(S[2*jc][0],   c0), sexp(S[2*jc][1],   c0));
            P[jc][1] = packh2(sexp(S[2*jc][2],   c1), sexp(S[2*jc][3],   c1));
            P[jc][2] = packh2(sexp(S[2*jc+1][0], c0), sexp(S[2*jc+1][1], c0));
            P[jc][3] = packh2(sexp(S[2*jc+1][2], c1), sexp(S[2*jc+1][3], c1));
        }

        float lf[4] = {0.0f, 0.0f, 0.0f, 0.0f};
        #pragma unroll
        for (int jc = 0; jc < 4; jc++)
            mma16816(lf, P[jc][0], P[jc][1], P[jc][2], P[jc][3], ONES, ONES);
        lrow0 = lrow0 * sc0 + lf[0];
        lrow1 = lrow1 * sc1 + lf[2];

        #pragma unroll
        for (int dc = 0; dc < 8; dc++) {
            Of[dc][0] *= sc0; Of[dc][1] *= sc0;
            Of[dc][2] *= sc1; Of[dc][3] *= sc1;
        }

        #pragma unroll
        for (int jc = 0; jc < 4; jc++) {
            int vrow = jc * 16 + (lane & 15);
            int vcb  = (lane >> 4) * 8;
            #pragma unroll
            for (int dcp = 0; dcp < 4; dcp++) {
                unsigned vb[4];
                ldm4t(vb, vsb + (vrow * SM_STRIDE + dcp * 16 + vcb) * 2);
                mma16816(Of[2*dcp],     P[jc][0], P[jc][1], P[jc][2], P[jc][3], vb[0], vb[1]);
                mma16816(Of[2*dcp + 1], P[jc][0], P[jc][1], P[jc][2], P[jc][3], vb[2], vb[3]);
            }
        }

        if (it + 1 < 64) {
            asm volatile("cp.async.wait_group 0;\n");
            __syncthreads();
        }
    }

    float inv0 = 1.0f / lrow0, inv1 = 1.0f / lrow1;
    int m = m0 + (w << 4) + gid;
    #pragma unroll
    for (int dc = 0; dc < 8; dc++) {
        int d0 = dc * 8 + tig * 2;
        g_O[(b * 64 + d0)     * NDS + m]     = Of[dc][0] * inv0;
        g_O[(b * 64 + d0 + 1) * NDS + m]     = Of[dc][1] * inv0;
        g_O[(b * 64 + d0)     * NDS + m + 8] = Of[dc][2] * inv1;
        g_O[(b * 64 + d0 + 1) * NDS + m + 8] = Of[dc][3] * inv1;
    }
}

// ============================================================================
// K4: convout — ROUND 8: 128 threads, 128-px tiles, precomputed f16 weights,
// cp.async staging ring; runs concurrently with attn via PDL, waits
// (griddepcontrol.wait) only before the g_O/g_efd epilogue.
// ============================================================================
#define CO_OFF_WH  0
#define CO_OFF_WL  25600
#define CO_OFF_STG 51200
#define CO_STG_BUF 8192                  // 16 ch x 128 px f32
#define CO_OFF_ACT 67584
#define CO_ACT_BUF 4352                  // [16][136] f16
#define CONVOUT_SMEM 76288

__device__ __forceinline__ void co_issue_stage(
    const float* __restrict__ x1, const float* __restrict__ x2,
    int b, int p0, int t, unsigned dstbase, int ks)
{
    #pragma unroll
    for (int rep = 0; rep < 4; rep++) {
        int i = t + rep * 128;           // 0..511 (16B units)
        int row = i >> 5, off = i & 31;
        int c = ks * 16 + row;
        const float* src = (c < 128) ? x1 + (size_t)(b * 128 + c) * HW
                                     : x2 + (size_t)(b * 64 + c - 128) * HW;
        cpasync16(dstbase + row * 512 + off * 16, src + p0 + off * 4);
    }
    asm volatile("cp.async.commit_group;\n");
}

__device__ __forceinline__ void co_convert(const float* stg, __half* AH, int t)
{
    #pragma unroll
    for (int ch = 0; ch < 4; ch++) {
        int i = ch * 512 + t * 4;        // 0..2047
        int row = i >> 7, col = i & 127;
        float4 v = *(const float4*)(stg + i);
        __half2 h0 = __floats2half2_rn(v.x, v.y);
        __half2 h1 = __floats2half2_rn(v.z, v.w);
        uint2 u;
        u.x = *(unsigned*)&h0;
        u.y = *(unsigned*)&h1;
        *(uint2*)&AH[row * 136 + col] = u;
    }
}

__global__ __launch_bounds__(128) void convout_kernel(
    const float* __restrict__ x1, const float* __restrict__ x2,
    const float* __restrict__ bias,
    const float* __restrict__ gamma, float* __restrict__ out)
{
    extern __shared__ char smc[];
    unsigned smu = (unsigned)__cvta_generic_to_shared(smc);

    int t = threadIdx.x;
    int lane = t & 31, wp = t >> 5;
    int ln15 = lane & 15, hb8 = (lane >> 4) * 8;
    int bx = blockIdx.x, b = blockIdx.y;
    int y = bx >> 1, xh = bx & 1;
    int p0 = (y << 8) + (xh << 7);
    int ndbase = ((y >> 2) << 6) + (xh << 5);

    // group 0: weights (precomputed f16 hi/lo) + activation stage 0
    #pragma unroll
    for (int rep = 0; rep < 13; rep++) {
        int i = t + rep * 128;
        if (i < 1600) {
            cpasync16(smu + CO_OFF_WH + i * 16, (const char*)g_wh + i * 16);
            cpasync16(smu + CO_OFF_WL + i * 16, (const char*)g_wl + i * 16);
        }
    }
    co_issue_stage(x1, x2, b, p0, t, smu + CO_OFF_STG, 0);                // group 0
    co_issue_stage(x1, x2, b, p0, t, smu + CO_OFF_STG + CO_STG_BUF, 1);   // group 1

    asm volatile("cp.async.wait_group 1;\n");   // group 0 (weights + stage 0) landed
    __syncthreads();
    co_convert((const float*)(smc + CO_OFF_STG), (__half*)(smc + CO_OFF_ACT), t);

    float acc[4][4][4];
    #pragma unroll
    for (int mt = 0; mt < 4; mt++)
        #pragma unroll
        for (int nb = 0; nb < 4; nb++)
            #pragma unroll
            for (int q = 0; q < 4; q++) acc[mt][nb][q] = 0.0f;

    unsigned whB = smu + CO_OFF_WH + (ln15 * 200 + hb8) * 2;
    unsigned wlB = smu + CO_OFF_WL + (ln15 * 200 + hb8) * 2;

    #pragma unroll 1
    for (int ks = 0; ks < 12; ks++) {
        __syncthreads();
        if (ks + 2 < 12)
            co_issue_stage(x1, x2, b, p0, t,
                           smu + CO_OFF_STG + (ks & 1) * CO_STG_BUF, ks + 2);

        unsigned actH = smu + CO_OFF_ACT + (ks & 1) * CO_ACT_BUF +
                        (ln15 * 136 + wp * 32 + hb8) * 2;
        unsigned Bh[8], A[4][4];
        ldm4t(Bh,     actH);
        ldm4t(Bh + 4, actH + 32);
        #pragma unroll
        for (int mt = 0; mt < 4; mt++)
            ldm4(A[mt], whB + mt * 6400 + ks * 32);
        #pragma unroll
        for (int mt = 0; mt < 4; mt++) {
            mma16816(acc[mt][0], A[mt][0], A[mt][1], A[mt][2], A[mt][3], Bh[0], Bh[1]);
            mma16816(acc[mt][1], A[mt][0], A[mt][1], A[mt][2], A[mt][3], Bh[2], Bh[3]);
            mma16816(acc[mt][2], A[mt][0], A[mt][1], A[mt][2], A[mt][3], Bh[4], Bh[5]);
            mma16816(acc[mt][3], A[mt][0], A[mt][1], A[mt][2], A[mt][3], Bh[6], Bh[7]);
        }
        #pragma unroll
        for (int mt = 0; mt < 4; mt++)
            ldm4(A[mt], wlB + mt * 6400 + ks * 32);
        #pragma unroll
        for (int mt = 0; mt < 4; mt++) {
            mma16816(acc[mt][0], A[mt][0], A[mt][1], A[mt][2], A[mt][3], Bh[0], Bh[1]);
            mma16816(acc[mt][1], A[mt][0], A[mt][1], A[mt][2], A[mt][3], Bh[2], Bh[3]);
            mma16816(acc[mt][2], A[mt][0], A[mt][1], A[mt][2], A[mt][3], Bh[4], Bh[5]);
            mma16816(acc[mt][3], A[mt][0], A[mt][1], A[mt][2], A[mt][3], Bh[6], Bh[7]);
        }

        if (ks + 1 < 12) {
            if (ks + 2 < 12) { asm volatile("cp.async.wait_group 1;\n"); }
            else             { asm volatile("cp.async.wait_group 0;\n"); }
            co_convert((const float*)(smc + CO_OFF_STG + ((ks + 1) & 1) * CO_STG_BUF),
                       (__half*)(smc + CO_OFF_ACT + ((ks + 1) & 1) * CO_ACT_BUF), t);
        }
    }

    // wait for attn (PDL primary) before touching g_O / anything ordered after it
    asm volatile("griddepcontrol.wait;" ::: "memory");
    __syncthreads();

    float* OS = (float*)(smc + CO_OFF_STG);      // [64][36]
    float* ES = OS + 64 * 36;                    // [64][36]
    {
        int o = t >> 1, c0 = (t & 1) << 4;
        const float* po = g_O   + (size_t)(b * 64 + o) * NDS + ndbase + c0;
        const float* pe = g_efd + (size_t)(b * 64 + o) * NDS + ndbase + c0;
        #pragma unroll
        for (int j = 0; j < 4; j++) {
            *(float4*)&OS[o * 36 + c0 + 4 * j] = *(const float4*)(po + 4 * j);
            *(float4*)&ES[o * 36 + c0 + 4 * j] = *(const float4*)(pe + 4 * j);
        }
    }
    __syncthreads();

    float tg = THITA_F * __ldg(gamma);
    int g = lane >> 2, tig = lane & 3;
    #pragma unroll
    for (int mt = 0; mt < 4; mt++) {
        int o = mt * 16 + g;
        float bb0 = __ldg(&bias[o]), bb1 = __ldg(&bias[o + 8]);
        #pragma unroll
        for (int nb = 0; nb < 4; nb++) {
            int pxl = wp * 32 + nb * 8 + tig * 2;
            int ndc = pxl >> 2;
            float a0 = tg * OS[o * 36 + ndc];
            float a1 = tg * OS[(o + 8) * 36 + ndc];
            float2 r0 = make_float2(fmaxf(acc[mt][nb][0] + bb0, 0.0f) + a0,
                                    fmaxf(acc[mt][nb][1] + bb0, 0.0f) + a0);
            float2 r1 = make_float2(fmaxf(acc[mt][nb][2] + bb1, 0.0f) + a1,
                                    fmaxf(acc[mt][nb][3] + bb1, 0.0f) + a1);
            *(float2*)(out + (size_t)(b * 64 + o)     * HW + p0 + pxl) = r0;
            *(float2*)(out + (size_t)(b * 64 + o + 8) * HW + p0 + pxl) = r1;
        }
    }

    int xq = t & 31, oo = t >> 5;
    #pragma unroll
    for (int rep = 0; rep < 16; rep++) {
        int o = rep * 4 + oo;
        float v = ES[o * 36 + xq];
        *(float4*)(out + OUT2OFF + (size_t)(b * 64 + o) * HW + p0 + (xq << 2)) =
            make_float4(v, v, v, v);
    }
}

// ============================================================================
extern "C" void kernel_launch(void* const* d_in, const int* in_sizes, int n_in,
                              void* d_out, int out_size)
{
    const float* x1    = (const float*)d_in[0];
    const float* x2    = (const float*)d_in[1];
    const float* ev    = (const float*)d_in[2];
    const float* xw0   = (const float*)d_in[3];
    const float* xb0   = (const float*)d_in[4];
    const float* xw1   = (const float*)d_in[5];
    const float* xb1   = (const float*)d_in[6];
    const float* ew0   = (const float*)d_in[7];
    const float* eb0   = (const float*)d_in[8];
    const float* ew1   = (const float*)d_in[9];
    const float* eb1   = (const float*)d_in[10];
    const float* qw    = (const float*)d_in[11];
    const float* qb    = (const float*)d_in[12];
    const float* kw    = (const float*)d_in[13];
    const float* kb    = (const float*)d_in[14];
    const float* vw    = (const float*)d_in[15];
    const float* vb    = (const float*)d_in[16];
    const float* gamma = (const float*)d_in[17];
    float* out = (float*)d_out;

    cudaFuncSetAttribute(prep_kernel,
                         cudaFuncAttributeMaxDynamicSharedMemorySize, PREP_SMEM);
    cudaFuncSetAttribute(qkv_kernel,
                         cudaFuncAttributeMaxDynamicSharedMemorySize, QKV_SMEM);
    cudaFuncSetAttribute(attn_kernel,
                         cudaFuncAttributeMaxDynamicSharedMemorySize, ATTN_SMEM);
    cudaFuncSetAttribute(convout_kernel,
                         cudaFuncAttributeMaxDynamicSharedMemorySize, CONVOUT_SMEM);

    wconv_kernel<<<48, 256>>>(xw0);
    prep_kernel<<<dim3(NDS / 64, BATCH, 2), 128, PREP_SMEM>>>(
        x1, x2, ev, xw0, xb0, ew0, eb0, ew1, eb1);
    qkv_kernel<<<dim3(NDS / 64, BATCH), 128, QKV_SMEM>>>(
        xw1, xb1, qw, qb, kw, kb, vw, vb);
    attn_kernel<<<dim3(NDS / 128, BATCH), 256, ATTN_SMEM>>>();

    // convout launched as a PDL secondary: starts while attn runs, its
    // epilogue gates on griddepcontrol.wait.
    {
        cudaLaunchConfig_t cfg = {};
        cfg.gridDim = dim3(512, BATCH, 1);
        cfg.blockDim = dim3(128, 1, 1);
        cfg.dynamicSmemBytes = CONVOUT_SMEM;
        cfg.stream = 0;
        cudaLaunchAttribute attrs[1];
        attrs[0].id = cudaLaunchAttributeProgrammaticStreamSerialization;
        attrs[0].val.programmaticStreamSerializationAllowed = 1;
        cfg.attrs = attrs;
        cfg.numAttrs = 1;
        cudaLaunchKernelEx(&cfg, convout_kernel, x1, x2, xb0, gamma, out);
    }
}

// round 9
// speedup vs baseline: 1.4491x; 1.0177x over previous
#include <cuda_runtime.h>
#include <cuda_fp16.h>
#include <math.h>

#define BATCH 4
#define CHN 64
#define HW 65536        // 256*256
#define NDS 4096        // 64*64 downsampled pixels
#define THITA_F 1.0e-4f
#define OUT2OFF (BATCH * CHN * HW)

// ---------------- scratch (device globals) ----------------------------------
__device__ __half g_xdsh[BATCH * CHN * NDS];    // down4(x) f16 [b][c][n]
__device__ float  g_efd [BATCH * CHN * NDS];    // ef ds fp32 [b][c][n] (feeds ef_up)
__device__ __half g_efdh[BATCH * CHN * NDS];    // ef ds f16 [b][c][n] (feeds k conv)
__device__ __half g_qh[BATCH * NDS * CHN];      // [b][n][d] f16
__device__ __half g_kh[BATCH * NDS * CHN];
__device__ __half g_vh[BATCH * NDS * CHN];
__device__ float  g_O[BATCH * CHN * NDS];       // attention output [b][d][m]
__device__ __half g_wh[64 * 200];               // conv0 weights f16 hi [o][c pad 200]
__device__ __half g_wl[64 * 200];               // conv0 weights f16 lo

// ============================================================================
// mma / ldmatrix helpers
// ============================================================================
__device__ __forceinline__ void mma16816(float* d,
    unsigned a0, unsigned a1, unsigned a2, unsigned a3,
    unsigned b0, unsigned b1)
{
    asm volatile(
        "mma.sync.aligned.m16n8k16.row.col.f32.f16.f16.f32 "
        "{%0,%1,%2,%3}, {%4,%5,%6,%7}, {%8,%9}, {%0,%1,%2,%3};\n"
        : "+f"(d[0]), "+f"(d[1]), "+f"(d[2]), "+f"(d[3])
        : "r"(a0), "r"(a1), "r"(a2), "r"(a3), "r"(b0), "r"(b1));
}
__device__ __forceinline__ void ldm4(unsigned* r, unsigned a) {
    asm volatile("ldmatrix.sync.aligned.m8n8.x4.shared.b16 {%0,%1,%2,%3}, [%4];\n"
        : "=r"(r[0]), "=r"(r[1]), "=r"(r[2]), "=r"(r[3]) : "r"(a));
}
__device__ __forceinline__ void ldm4t(unsigned* r, unsigned a) {
    asm volatile("ldmatrix.sync.aligned.m8n8.x4.trans.shared.b16 {%0,%1,%2,%3}, [%4];\n"
        : "=r"(r[0]), "=r"(r[1]), "=r"(r[2]), "=r"(r[3]) : "r"(a));
}
__device__ __forceinline__ void cpasync16(unsigned dst, const void* src) {
    asm volatile("cp.async.cg.shared.global [%0], [%1], 16;\n"
        :: "r"(dst), "l"(src));
}
__device__ __forceinline__ unsigned hpack(__half a, __half b) {
    __half2 h = __halves2half2(a, b);
    return *(unsigned*)&h;
}
__device__ __forceinline__ unsigned packh2(float a, float b) {
    __half2 h = __floats2half2_rn(a, b);
    return *(unsigned*)&h;
}
__device__ __forceinline__ float sexp(float s, float c) {
    float t = fmaf(s, 12102203.16f, c);
    t = fmaxf(t, 0.0f);
    return __int_as_float(__float2int_rn(t));
}

// single-pass f16 GEMM: acc[8][4] += W(16 rows at wb) @ act(K=16*nks x 64, stride 72)
__device__ __forceinline__ void gemm1p(float acc[8][4], unsigned wb, int wstride,
                                       unsigned ab, int nks, int lane)
{
    int ln15 = lane & 15, hb8 = (lane >> 4) * 8;
    unsigned wl = wb + (ln15 * wstride + hb8) * 2;
    #pragma unroll
    for (int ks = 0; ks < nks; ks++) {
        unsigned al = ab + ((ks * 16 + ln15) * 72 + hb8) * 2;
        unsigned B[16], A[4];
        ldm4t(B,      al);
        ldm4t(B + 4,  al + 32);
        ldm4t(B + 8,  al + 64);
        ldm4t(B + 12, al + 96);
        ldm4(A, wl + ks * 32);
        #pragma unroll
        for (int nc = 0; nc < 8; nc++) {
            int ib = (nc >> 1) * 4 + (nc & 1) * 2;
            mma16816(acc[nc], A[0], A[1], A[2], A[3], B[ib], B[ib + 1]);
        }
    }
}

// 3-pass hi/lo GEMM (K=64): acc += Wh@Ah + Wh@Al + Wl@Ah
__device__ __forceinline__ void gemm3p(float acc[8][4],
    unsigned wh, unsigned wlo, unsigned ah, unsigned alo, int lane)
{
    int ln15 = lane & 15, hb8 = (lane >> 4) * 8;
    unsigned wbh = wh  + (ln15 * 72 + hb8) * 2;
    unsigned wbl = wlo + (ln15 * 72 + hb8) * 2;
    #pragma unroll
    for (int ks = 0; ks < 4; ks++) {
        unsigned abh = ah  + ((ks * 16 + ln15) * 72 + hb8) * 2;
        unsigned abl = alo + ((ks * 16 + ln15) * 72 + hb8) * 2;
        unsigned Bh[16], Bl[16], Wf[4], Lf[4];
        ldm4t(Bh,      abh);
        ldm4t(Bh + 4,  abh + 32);
        ldm4t(Bh + 8,  abh + 64);
        ldm4t(Bh + 12, abh + 96);
        ldm4t(Bl,      abl);
        ldm4t(Bl + 4,  abl + 32);
        ldm4t(Bl + 8,  abl + 64);
        ldm4t(Bl + 12, abl + 96);
        ldm4(Wf, wbh + ks * 32);
        ldm4(Lf, wbl + ks * 32);
        #pragma unroll
        for (int nc = 0; nc < 8; nc++) {
            int ib = (nc >> 1) * 4 + (nc & 1) * 2;
            mma16816(acc[nc], Wf[0], Wf[1], Wf[2], Wf[3], Bh[ib], Bh[ib + 1]);
            mma16816(acc[nc], Wf[0], Wf[1], Wf[2], Wf[3], Bl[ib], Bl[ib + 1]);
            mma16816(acc[nc], Lf[0], Lf[1], Lf[2], Lf[3], Bh[ib], Bh[ib + 1]);
        }
    }
}

// ============================================================================
// K0: wconv — one-time conv0 weight split to f16 hi/lo globals
// ============================================================================
__global__ void wconv_kernel(const float* __restrict__ w)
{
    int i = blockIdx.x * 256 + threadIdx.x;
    if (i < 12288) {
        int o = i / 192, c = i - o * 192;
        float v = w[i];
        __half h = __float2half_rn(v);
        g_wh[o * 200 + c] = h;
        g_wl[o * 200 + c] = __float2half_rn(v - __half2float(h));
    }
}

// ============================================================================
// K1: prep — z=0: conv0_ds (f16 1-pass) -> g_xdsh; z=1: ef chain (3-pass)
// ============================================================================
#define PREP_SMEM (64 * 200 * 2 + 192 * 72 * 2)   // 53248

__global__ __launch_bounds__(128) void prep_kernel(
    const float* __restrict__ x1, const float* __restrict__ x2,
    const float* __restrict__ ev,
    const float* __restrict__ xw0, const float* __restrict__ xb0,
    const float* __restrict__ ew0, const float* __restrict__ eb0,
    const float* __restrict__ ew1, const float* __restrict__ eb1)
{
    extern __shared__ char smc[];
    unsigned smu = (unsigned)__cvta_generic_to_shared(smc);
    int t = threadIdx.x, lane = t & 31, w = t >> 5;
    int gid = lane >> 2, tig = lane & 3;
    int blk = blockIdx.x, b = blockIdx.y;
    int n0 = blk << 6;

    float acc[8][4];
    #pragma unroll
    for (int nc = 0; nc < 8; nc++)
        #pragma unroll
        for (int q = 0; q < 4; q++) acc[nc][q] = 0.0f;

    if (blockIdx.z == 0) {
        __half* W  = (__half*)smc;
        __half* Ac = (__half*)(smc + 64 * 200 * 2);
        for (int i = t; i < 12288; i += 128) {
            int o = i / 192, c = i - o * 192;
            W[o * 200 + c] = __float2half_rn(xw0[i]);
        }
        for (int i = t; i < 12288; i += 128) {
            int c = i >> 6, x = i & 63;
            const float* s = (c < 128) ? x1 + (size_t)(b * 128 + c) * HW
                                       : x2 + (size_t)(b * 64 + c - 128) * HW;
            Ac[c * 72 + x] = __float2half_rn(s[(blk << 10) + (x << 2)]);
        }
        __syncthreads();

        gemm1p(acc, smu + (w * 16) * 200 * 2, 200,
               smu + 64 * 200 * 2, 12, lane);

        int o = (w << 4) + gid;
        float b0 = __ldg(&xb0[o]), b1 = __ldg(&xb0[o + 8]);
        #pragma unroll
        for (int nc = 0; nc < 8; nc++) {
            int n = n0 + nc * 8 + tig * 2;
            *(__half2*)&g_xdsh[(size_t)(b * 64 + o) * NDS + n] =
                __floats2half2_rn(fmaxf(acc[nc][0] + b0, 0.0f),
                                  fmaxf(acc[nc][1] + b0, 0.0f));
            *(__half2*)&g_xdsh[(size_t)(b * 64 + o + 8) * NDS + n] =
                __floats2half2_rn(fmaxf(acc[nc][2] + b1, 0.0f),
                                  fmaxf(acc[nc][3] + b1, 0.0f));
        }
    } else {
        __half* Wh = (__half*)smc;
        __half* Wl = Wh + 64 * 72;
        __half* Ah = Wl + 64 * 72;
        __half* Al = Ah + 64 * 72;
        unsigned oWh = smu, oWl = smu + 9216, oAh = smu + 18432, oAl = smu + 27648;

        for (int i = t; i < 4096; i += 128) {
            float v = ew0[i];
            __half h = __float2half_rn(v);
            int o = i >> 6, c = i & 63;
            Wh[o * 72 + c] = h;
            Wl[o * 72 + c] = __float2half_rn(v - __half2float(h));
        }
        for (int i = t; i < 4096; i += 128) {
            int c = i >> 6, x = i & 63;
            float v = ev[(size_t)(b * 64 + c) * HW + (blk << 10) + (x << 2)];
            __half h = __float2half_rn(v);
            Ah[c * 72 + x] = h;
            Al[c * 72 + x] = __float2half_rn(v - __half2float(h));
        }
        __syncthreads();

        gemm3p(acc, oWh + (w * 16) * 144, oWl + (w * 16) * 144, oAh, oAl, lane);
        __syncthreads();

        {
            int o = (w << 4) + gid;
            float b0 = __ldg(&eb0[o]), b1 = __ldg(&eb0[o + 8]);
            #pragma unroll
            for (int nc = 0; nc < 8; nc++) {
                int px = nc * 8 + tig * 2;
                float t0 = fmaxf(acc[nc][0] + b0, 0.0f);
                float t1 = fmaxf(acc[nc][1] + b0, 0.0f);
                float t2 = fmaxf(acc[nc][2] + b1, 0.0f);
                float t3 = fmaxf(acc[nc][3] + b1, 0.0f);
                __half h0 = __float2half_rn(t0), h1 = __float2half_rn(t1);
                __half h2 = __float2half_rn(t2), h3 = __float2half_rn(t3);
                *(__half2*)&Ah[o * 72 + px] = __halves2half2(h0, h1);
                *(__half2*)&Al[o * 72 + px] = __floats2half2_rn(
                    t0 - __half2float(h0), t1 - __half2float(h1));
                *(__half2*)&Ah[(o + 8) * 72 + px] = __halves2half2(h2, h3);
                *(__half2*)&Al[(o + 8) * 72 + px] = __floats2half2_rn(
                    t2 - __half2float(h2), t3 - __half2float(h3));
            }
        }
        for (int i = t; i < 4096; i += 128) {
            float v = ew1[i];
            __half h = __float2half_rn(v);
            int o = i >> 6, c = i & 63;
            Wh[o * 72 + c] = h;
            Wl[o * 72 + c] = __float2half_rn(v - __half2float(h));
        }
        __syncthreads();

        #pragma unroll
        for (int nc = 0; nc < 8; nc++)
            #pragma unroll
            for (int q = 0; q < 4; q++) acc[nc][q] = 0.0f;
        gemm3p(acc, oWh + (w * 16) * 144, oWl + (w * 16) * 144, oAh, oAl, lane);

        int o = (w << 4) + gid;
        float b0 = __ldg(&eb1[o]), b1 = __ldg(&eb1[o + 8]);
        #pragma unroll
        for (int nc = 0; nc < 8; nc++) {
            int n = n0 + nc * 8 + tig * 2;
            float r0 = fmaxf(acc[nc][0] + b0, 0.0f);
            float r1 = fmaxf(acc[nc][1] + b0, 0.0f);
            float r2 = fmaxf(acc[nc][2] + b1, 0.0f);
            float r3 = fmaxf(acc[nc][3] + b1, 0.0f);
            *(float2*)&g_efd[(size_t)(b * 64 + o) * NDS + n]     = make_float2(r0, r1);
            *(float2*)&g_efd[(size_t)(b * 64 + o + 8) * NDS + n] = make_float2(r2, r3);
            *(__half2*)&g_efdh[(size_t)(b * 64 + o) * NDS + n]     = __floats2half2_rn(r0, r1);
            *(__half2*)&g_efdh[(size_t)(b * 64 + o + 8) * NDS + n] = __floats2half2_rn(r2, r3);
        }
    }
}

// ============================================================================
// K2: qkv — all f16 1-pass mma (unchanged)
// ============================================================================
#define QKV_SMEM (4 * 64 * 72 * 2)

__global__ __launch_bounds__(128) void qkv_kernel(
    const float* __restrict__ xw1, const float* __restrict__ xb1,
    const float* __restrict__ qw,  const float* __restrict__ qb,
    const float* __restrict__ kw,  const float* __restrict__ kb,
    const float* __restrict__ vw,  const float* __restrict__ vb)
{
    extern __shared__ char smc[];
    unsigned smu = (unsigned)__cvta_generic_to_shared(smc);
    __half* W   = (__half*)smc;
    __half* Act = W + 64 * 72;
    __half* Tb  = Act + 64 * 72;
    __half* Tr  = Tb + 64 * 72;
    unsigned oW = smu, oAct = smu + 9216, oTb = smu + 18432;

    int t = threadIdx.x, lane = t & 31, w = t >> 5;
    int gid = lane >> 2, tig = lane & 3;
    int blk = blockIdx.x, b = blockIdx.y;
    int n0 = blk << 6;
    int o = (w << 4) + gid;

    for (int i = t; i < 512; i += 128) {
        int row = i >> 3, off = i & 7;
        *(uint4*)&Act[row * 72 + off * 8] =
            *(const uint4*)&g_xdsh[(size_t)(b * 64 + row) * NDS + n0 + off * 8];
    }
    for (int i = t; i < 4096; i += 128)
        W[(i >> 6) * 72 + (i & 63)] = __float2half_rn(xw1[i]);
    __syncthreads();

    float acc[8][4];
    #pragma unroll
    for (int nc = 0; nc < 8; nc++)
        #pragma unroll
        for (int q = 0; q < 4; q++) acc[nc][q] = 0.0f;
    gemm1p(acc, oW + (w * 16) * 144, 72, oAct, 4, lane);
    {
        float b0 = __ldg(&xb1[o]), b1 = __ldg(&xb1[o + 8]);
        #pragma unroll
        for (int nc = 0; nc < 8; nc++) {
            int px = nc * 8 + tig * 2;
            *(__half2*)&Tb[o * 72 + px] = __floats2half2_rn(
                fmaxf(acc[nc][0] + b0, 0.0f), fmaxf(acc[nc][1] + b0, 0.0f));
            *(__half2*)&Tb[(o + 8) * 72 + px] = __floats2half2_rn(
                fmaxf(acc[nc][2] + b1, 0.0f), fmaxf(acc[nc][3] + b1, 0.0f));
        }
    }
    __syncthreads();
    for (int i = t; i < 4096; i += 128)
        W[(i >> 6) * 72 + (i & 63)] = __float2half_rn(qw[i]);
    __syncthreads();

    #pragma unroll
    for (int nc = 0; nc < 8; nc++)
        #pragma unroll
        for (int q = 0; q < 4; q++) acc[nc][q] = 0.0f;
    gemm1p(acc, oW + (w * 16) * 144, 72, oTb, 4, lane);
    {
        float b0 = __ldg(&qb[o]), b1 = __ldg(&qb[o + 8]);
        #pragma unroll
        for (int nc = 0; nc < 8; nc++) {
            int px = nc * 8 + tig * 2;
            Tr[px * 72 + o]           = __float2half_rn(fmaxf(acc[nc][0] + b0, 0.0f));
            Tr[(px + 1) * 72 + o]     = __float2half_rn(fmaxf(acc[nc][1] + b0, 0.0f));
            Tr[px * 72 + o + 8]       = __float2half_rn(fmaxf(acc[nc][2] + b1, 0.0f));
            Tr[(px + 1) * 72 + o + 8] = __float2half_rn(fmaxf(acc[nc][3] + b1, 0.0f));
        }
    }
    __syncthreads();
    for (int i = t; i < 512; i += 128) {
        int row = i >> 3, off = i & 7;
        *(uint4*)&g_qh[((size_t)b * NDS + n0 + row) * 64 + off * 8] =
            *(uint4*)&Tr[row * 72 + off * 8];
    }
    for (int i = t; i < 4096; i += 128)
        W[(i >> 6) * 72 + (i & 63)] = __float2half_rn(vw[i]);
    __syncthreads();

    #pragma unroll
    for (int nc = 0; nc < 8; nc++)
        #pragma unroll
        for (int q = 0; q < 4; q++) acc[nc][q] = 0.0f;
    gemm1p(acc, oW + (w * 16) * 144, 72, oTb, 4, lane);
    {
        float b0 = __ldg(&vb[o]), b1 = __ldg(&vb[o + 8]);
        #pragma unroll
        for (int nc = 0; nc < 8; nc++) {
            int px = nc * 8 + tig * 2;
            Tr[px * 72 + o]           = __float2half_rn(fmaxf(acc[nc][0] + b0, 0.0f));
            Tr[(px + 1) * 72 + o]     = __float2half_rn(fmaxf(acc[nc][1] + b0, 0.0f));
            Tr[px * 72 + o + 8]       = __float2half_rn(fmaxf(acc[nc][2] + b1, 0.0f));
            Tr[(px + 1) * 72 + o + 8] = __float2half_rn(fmaxf(acc[nc][3] + b1, 0.0f));
        }
    }
    __syncthreads();
    for (int i = t; i < 512; i += 128) {
        int row = i >> 3, off = i & 7;
        *(uint4*)&g_vh[((size_t)b * NDS + n0 + row) * 64 + off * 8] =
            *(uint4*)&Tr[row * 72 + off * 8];
    }
    for (int i = t; i < 4096; i += 128)
        W[(i >> 6) * 72 + (i & 63)] = __float2half_rn(kw[i]);
    for (int i = t; i < 512; i += 128) {
        int row = i >> 3, off = i & 7;
        *(uint4*)&Act[row * 72 + off * 8] =
            *(const uint4*)&g_efdh[(size_t)(b * 64 + row) * NDS + n0 + off * 8];
    }
    __syncthreads();

    #pragma unroll
    for (int nc = 0; nc < 8; nc++)
        #pragma unroll
        for (int q = 0; q < 4; q++) acc[nc][q] = 0.0f;
    gemm1p(acc, oW + (w * 16) * 144, 72, oAct, 4, lane);
    {
        float b0 = __ldg(&kb[o]), b1 = __ldg(&kb[o + 8]);
        #pragma unroll
        for (int nc = 0; nc < 8; nc++) {
            int px = nc * 8 + tig * 2;
            Tr[px * 72 + o]           = __float2half_rn(fmaxf(acc[nc][0] + b0, 0.0f));
            Tr[(px + 1) * 72 + o]     = __float2half_rn(fmaxf(acc[nc][1] + b0, 0.0f));
            Tr[px * 72 + o + 8]       = __float2half_rn(fmaxf(acc[nc][2] + b1, 0.0f));
            Tr[(px + 1) * 72 + o + 8] = __float2half_rn(fmaxf(acc[nc][3] + b1, 0.0f));
        }
    }
    __syncthreads();
    for (int i = t; i < 512; i += 128) {
        int row = i >> 3, off = i & 7;
        *(uint4*)&g_kh[((size_t)b * NDS + n0 + row) * 64 + off * 8] =
            *(uint4*)&Tr[row * 72 + off * 8];
    }
}

// ============================================================================
// K3: flash attention — ROUND 9: 4 warps, 32 rows/warp (two 16-row subtiles
// sharing every K/V fragment => half the LDSM per m-row). M-tile 128.
// ============================================================================
#define SM_STRIDE 72
#define ATTN_SMEM ((128 * SM_STRIDE + 4 * 64 * SM_STRIDE) * 2)

__global__ __launch_bounds__(128, 2) void attn_kernel()
{
    extern __shared__ __half smh[];
    __half* qs  = smh;                       // 128 x 72
    __half* ks0 = smh + 128 * SM_STRIDE;     // 2 x 64 x 72
    __half* vs0 = ks0 + 2 * 64 * SM_STRIDE;  // 2 x 64 x 72

    int tid  = threadIdx.x;
    int lane = tid & 31, w = tid >> 5;       // w: 0..3
    int gid  = lane >> 2, tig = lane & 3;
    int b    = blockIdx.y;
    int m0   = blockIdx.x << 7;

    const __half* qg = g_qh + (size_t)b * NDS * 64;
    const __half* kg = g_kh + (size_t)b * NDS * 64;
    const __half* vg = g_vh + (size_t)b * NDS * 64;

    unsigned qs_base = (unsigned)__cvta_generic_to_shared(qs);
    unsigned ks_base = (unsigned)__cvta_generic_to_shared(ks0);
    unsigned vs_base = (unsigned)__cvta_generic_to_shared(vs0);

    #pragma unroll
    for (int rep = 0; rep < 4; rep++) {
        int c = tid + rep * 128;             // 0..511
        int row = c >> 3, off = c & 7;
        cpasync16(ks_base + (row * SM_STRIDE + off * 8) * 2, kg + row * 64 + off * 8);
        cpasync16(vs_base + (row * SM_STRIDE + off * 8) * 2, vg + row * 64 + off * 8);
    }
    asm volatile("cp.async.commit_group;\n");

    // PDL: allow the dependent convout grid to start now
    asm volatile("griddepcontrol.launch_dependents;" ::: "memory");

    for (int c = tid; c < 1024; c += 128) {
        int row = c >> 3, off = c & 7;
        *(uint4*)(qs + row * SM_STRIDE + off * 8) =
            *(const uint4*)(qg + (size_t)(m0 + row) * 64 + off * 8);
    }
    asm volatile("cp.async.wait_group 0;\n");
    __syncthreads();

    // Q fragments for both 16-row subtiles of this warp's 32 rows
    unsigned qa[2][4][4];
    #pragma unroll
    for (int s = 0; s < 2; s++) {
        int row = (w << 5) + (s << 4) + (lane & 15);
        #pragma unroll
        for (int kc = 0; kc < 4; kc++) {
            int dof = kc * 16 + (lane >> 4) * 8;
            ldm4(qa[s][kc], qs_base + (row * SM_STRIDE + dof) * 2);
        }
    }

    float Of[2][8][4];
    #pragma unroll
    for (int s = 0; s < 2; s++)
        #pragma unroll
        for (int dc = 0; dc < 8; dc++)
            #pragma unroll
            for (int q = 0; q < 4; q++) Of[s][dc][q] = 0.0f;
    float mrow[2][2], lrow[2][2];
    #pragma unroll
    for (int s = 0; s < 2; s++) {
        mrow[s][0] = -1e30f; mrow[s][1] = -1e30f;
        lrow[s][0] = 0.0f;   lrow[s][1] = 0.0f;
    }
    const unsigned ONES = 0x3C003C00u;

    for (int it = 0; it < 64; it++) {
        int bf = it & 1;
        unsigned ksb = ks_base + bf * 64 * SM_STRIDE * 2;
        unsigned vsb = vs_base + bf * 64 * SM_STRIDE * 2;

        if (it + 1 < 64) {
            int n0n = (it + 1) << 6;
            int nb  = (it + 1) & 1;
            #pragma unroll
            for (int rep = 0; rep < 4; rep++) {
                int c = tid + rep * 128;
                int row = c >> 3, off = c & 7;
                cpasync16(ks_base + (nb * 64 * SM_STRIDE + row * SM_STRIDE + off * 8) * 2,
                          kg + (size_t)(n0n + row) * 64 + off * 8);
                cpasync16(vs_base + (nb * 64 * SM_STRIDE + row * SM_STRIDE + off * 8) * 2,
                          vg + (size_t)(n0n + row) * 64 + off * 8);
            }
            asm volatile("cp.async.commit_group;\n");
        }

        // S = Q @ K^T : K fragments shared by both subtiles
        float S[2][8][4];
        #pragma unroll
        for (int nc = 0; nc < 8; nc++) {
            unsigned kb[8];
            int krow = nc * 8 + (lane & 7);
            int kd   = (lane >> 3) * 8;
            ldm4(kb,     ksb + (krow * SM_STRIDE + kd) * 2);
            ldm4(kb + 4, ksb + (krow * SM_STRIDE + 32 + kd) * 2);
            #pragma unroll
            for (int s = 0; s < 2; s++) {
                #pragma unroll
                for (int q = 0; q < 4; q++) S[s][nc][q] = 0.0f;
                mma16816(S[s][nc], qa[s][0][0], qa[s][0][1], qa[s][0][2], qa[s][0][3], kb[0], kb[1]);
                mma16816(S[s][nc], qa[s][1][0], qa[s][1][1], qa[s][1][2], qa[s][1][3], kb[2], kb[3]);
                mma16816(S[s][nc], qa[s][2][0], qa[s][2][1], qa[s][2][2], qa[s][2][3], kb[4], kb[5]);
                mma16816(S[s][nc], qa[s][3][0], qa[s][3][1], qa[s][3][2], qa[s][3][3], kb[6], kb[7]);
            }
        }

        // online softmax + pack P, per subtile
        unsigned P[2][4][4];
        #pragma unroll
        for (int s = 0; s < 2; s++) {
            float tm0 = fmaxf(S[s][0][0], S[s][0][1]);
            float tm1 = fmaxf(S[s][0][2], S[s][0][3]);
            #pragma unroll
            for (int nc = 1; nc < 8; nc++) {
                tm0 = fmaxf(tm0, fmaxf(S[s][nc][0], S[s][nc][1]));
                tm1 = fmaxf(tm1, fmaxf(S[s][nc][2], S[s][nc][3]));
            }
            tm0 = fmaxf(tm0, __shfl_xor_sync(0xffffffffu, tm0, 1));
            tm0 = fmaxf(tm0, __shfl_xor_sync(0xffffffffu, tm0, 2));
            tm1 = fmaxf(tm1, __shfl_xor_sync(0xffffffffu, tm1, 1));
            tm1 = fmaxf(tm1, __shfl_xor_sync(0xffffffffu, tm1, 2));
            float nm0 = fmaxf(mrow[s][0], tm0), nm1 = fmaxf(mrow[s][1], tm1);
            float sc0 = exp2f((mrow[s][0] - nm0) * 1.44269504f);
            float sc1 = exp2f((mrow[s][1] - nm1) * 1.44269504f);
            mrow[s][0] = nm0; mrow[s][1] = nm1;
            float c0 = 1064866805.0f - nm0 * 12102203.16f;
            float c1 = 1064866805.0f - nm1 * 12102203.16f;

            #pragma unroll
            for (int jc = 0; jc < 4; jc++) {
                P[s][jc][0] = packh2(sexp(S[s][2*jc][0],   c0), sexp(S[s][2*jc][1],   c0));
                P[s][jc][1] = packh2(sexp(S[s][2*jc][2],   c1), sexp(S[s][2*jc][3],   c1));
                P[s][jc][2] = packh2(sexp(S[s][2*jc+1][0], c0), sexp(S[s][2*jc+1][1], c0));
                P[s][jc][3] = packh2(sexp(S[s][2*jc+1][2], c1), sexp(S[s][2*jc+1][3], c1));
            }

            float lf[4] = {0.0f, 0.0f, 0.0f, 0.0f};
            #pragma unroll
            for (int jc = 0; jc < 4; jc++)
                mma16816(lf, P[s][jc][0], P[s][jc][1], P[s][jc][2], P[s][jc][3], ONES, ONES);
            lrow[s][0] = lrow[s][0] * sc0 + lf[0];
            lrow[s][1] = lrow[s][1] * sc1 + lf[2];

            #pragma unroll
            for (int dc = 0; dc < 8; dc++) {
                Of[s][dc][0] *= sc0; Of[s][dc][1] *= sc0;
                Of[s][dc][2] *= sc1; Of[s][dc][3] *= sc1;
            }
        }

        // O += P @ V : V fragments shared by both subtiles
        #pragma unroll
        for (int jc = 0; jc < 4; jc++) {
            int vrow = jc * 16 + (lane & 15);
            int vcb  = (lane >> 4) * 8;
            #pragma unroll
            for (int dcp = 0; dcp < 4; dcp++) {
                unsigned vb[4];
                ldm4t(vb, vsb + (vrow * SM_STRIDE + dcp * 16 + vcb) * 2);
                #pragma unroll
                for (int s = 0; s < 2; s++) {
                    mma16816(Of[s][2*dcp],     P[s][jc][0], P[s][jc][1], P[s][jc][2], P[s][jc][3], vb[0], vb[1]);
                    mma16816(Of[s][2*dcp + 1], P[s][jc][0], P[s][jc][1], P[s][jc][2], P[s][jc][3], vb[2], vb[3]);
                }
            }
        }

        if (it + 1 < 64) {
            asm volatile("cp.async.wait_group 0;\n");
            __syncthreads();
        }
    }

    #pragma unroll
    for (int s = 0; s < 2; s++) {
        float inv0 = 1.0f / lrow[s][0], inv1 = 1.0f / lrow[s][1];
        int m = m0 + (w << 5) + (s << 4) + gid;
        #pragma unroll
        for (int dc = 0; dc < 8; dc++) {
            int d0 = dc * 8 + tig * 2;
            g_O[(b * 64 + d0)     * NDS + m]     = Of[s][dc][0] * inv0;
            g_O[(b * 64 + d0 + 1) * NDS + m]     = Of[s][dc][1] * inv0;
            g_O[(b * 64 + d0)     * NDS + m + 8] = Of[s][dc][2] * inv1;
            g_O[(b * 64 + d0 + 1) * NDS + m + 8] = Of[s][dc][3] * inv1;
        }
    }
}

// ============================================================================
// K4: convout — 128 threads, cp.async ring, precomputed f16 weights, PDL wait
// ============================================================================
#define CO_OFF_WH  0
#define CO_OFF_WL  25600
#define CO_OFF_STG 51200
#define CO_STG_BUF 8192
#define CO_OFF_ACT 67584
#define CO_ACT_BUF 4352
#define CONVOUT_SMEM 76288

__device__ __forceinline__ void co_issue_stage(
    const float* __restrict__ x1, const float* __restrict__ x2,
    int b, int p0, int t, unsigned dstbase, int ks)
{
    #pragma unroll
    for (int rep = 0; rep < 4; rep++) {
        int i = t + rep * 128;
        int row = i >> 5, off = i & 31;
        int c = ks * 16 + row;
        const float* src = (c < 128) ? x1 + (size_t)(b * 128 + c) * HW
                                     : x2 + (size_t)(b * 64 + c - 128) * HW;
        cpasync16(dstbase + row * 512 + off * 16, src + p0 + off * 4);
    }
    asm volatile("cp.async.commit_group;\n");
}

__device__ __forceinline__ void co_convert(const float* stg, __half* AH, int t)
{
    #pragma unroll
    for (int ch = 0; ch < 4; ch++) {
        int i = ch * 512 + t * 4;
        int row = i >> 7, col = i & 127;
        float4 v = *(const float4*)(stg + i);
        __half2 h0 = __floats2half2_rn(v.x, v.y);
        __half2 h1 = __floats2half2_rn(v.z, v.w);
        uint2 u;
        u.x = *(unsigned*)&h0;
        u.y = *(unsigned*)&h1;
        *(uint2*)&AH[row * 136 + col] = u;
    }
}

__global__ __launch_bounds__(128) void convout_kernel(
    const float* __restrict__ x1, const float* __restrict__ x2,
    const float* __restrict__ bias,
    const float* __restrict__ gamma, float* __restrict__ out)
{
    extern __shared__ char smc[];
    unsigned smu = (unsigned)__cvta_generic_to_shared(smc);

    int t = threadIdx.x;
    int lane = t & 31, wp = t >> 5;
    int ln15 = lane & 15, hb8 = (lane >> 4) * 8;
    int bx = blockIdx.x, b = blockIdx.y;
    int y = bx >> 1, xh = bx & 1;
    int p0 = (y << 8) + (xh << 7);
    int ndbase = ((y >> 2) << 6) + (xh << 5);

    #pragma unroll
    for (int rep = 0; rep < 13; rep++) {
        int i = t + rep * 128;
        if (i < 1600) {
            cpasync16(smu + CO_OFF_WH + i * 16, (const char*)g_wh + i * 16);
            cpasync16(smu + CO_OFF_WL + i * 16, (const char*)g_wl + i * 16);
        }
    }
    co_issue_stage(x1, x2, b, p0, t, smu + CO_OFF_STG, 0);
    co_issue_stage(x1, x2, b, p0, t, smu + CO_OFF_STG + CO_STG_BUF, 1);

    asm volatile("cp.async.wait_group 1;\n");
    __syncthreads();
    co_convert((const float*)(smc + CO_OFF_STG), (__half*)(smc + CO_OFF_ACT), t);

    float acc[4][4][4];
    #pragma unroll
    for (int mt = 0; mt < 4; mt++)
        #pragma unroll
        for (int nb = 0; nb < 4; nb++)
            #pragma unroll
            for (int q = 0; q < 4; q++) acc[mt][nb][q] = 0.0f;

    unsigned whB = smu + CO_OFF_WH + (ln15 * 200 + hb8) * 2;
    unsigned wlB = smu + CO_OFF_WL + (ln15 * 200 + hb8) * 2;

    #pragma unroll 1
    for (int ks = 0; ks < 12; ks++) {
        __syncthreads();
        if (ks + 2 < 12)
            co_issue_stage(x1, x2, b, p0, t,
                           smu + CO_OFF_STG + (ks & 1) * CO_STG_BUF, ks + 2);

        unsigned actH = smu + CO_OFF_ACT + (ks & 1) * CO_ACT_BUF +
                        (ln15 * 136 + wp * 32 + hb8) * 2;
        unsigned Bh[8], A[4][4];
        ldm4t(Bh,     actH);
        ldm4t(Bh + 4, actH + 32);
        #pragma unroll
        for (int mt = 0; mt < 4; mt++)
            ldm4(A[mt], whB + mt * 6400 + ks * 32);
        #pragma unroll
        for (int mt = 0; mt < 4; mt++) {
            mma16816(acc[mt][0], A[mt][0], A[mt][1], A[mt][2], A[mt][3], Bh[0], Bh[1]);
            mma16816(acc[mt][1], A[mt][0], A[mt][1], A[mt][2], A[mt][3], Bh[2], Bh[3]);
            mma16816(acc[mt][2], A[mt][0], A[mt][1], A[mt][2], A[mt][3], Bh[4], Bh[5]);
            mma16816(acc[mt][3], A[mt][0], A[mt][1], A[mt][2], A[mt][3], Bh[6], Bh[7]);
        }
        #pragma unroll
        for (int mt = 0; mt < 4; mt++)
            ldm4(A[mt], wlB + mt * 6400 + ks * 32);
        #pragma unroll
        for (int mt = 0; mt < 4; mt++) {
            mma16816(acc[mt][0], A[mt][0], A[mt][1], A[mt][2], A[mt][3], Bh[0], Bh[1]);
            mma16816(acc[mt][1], A[mt][0], A[mt][1], A[mt][2], A[mt][3], Bh[2], Bh[3]);
            mma16816(acc[mt][2], A[mt][0], A[mt][1], A[mt][2], A[mt][3], Bh[4], Bh[5]);
            mma16816(acc[mt][3], A[mt][0], A[mt][1], A[mt][2], A[mt][3], Bh[6], Bh[7]);
        }

        if (ks + 1 < 12) {
            if (ks + 2 < 12) { asm volatile("cp.async.wait_group 1;\n"); }
            else             { asm volatile("cp.async.wait_group 0;\n"); }
            co_convert((const float*)(smc + CO_OFF_STG + ((ks + 1) & 1) * CO_STG_BUF),
                       (__half*)(smc + CO_OFF_ACT + ((ks + 1) & 1) * CO_ACT_BUF), t);
        }
    }

    asm volatile("griddepcontrol.wait;" ::: "memory");
    __syncthreads();

    float* OS = (float*)(smc + CO_OFF_STG);
    float* ES = OS + 64 * 36;
    {
        int o = t >> 1, c0 = (t & 1) << 4;
        const float* po = g_O   + (size_t)(b * 64 + o) * NDS + ndbase + c0;
        const float* pe = g_efd + (size_t)(b * 64 + o) * NDS + ndbase + c0;
        #pragma unroll
        for (int j = 0; j < 4; j++) {
            *(float4*)&OS[o * 36 + c0 + 4 * j] = *(const float4*)(po + 4 * j);
            *(float4*)&ES[o * 36 + c0 + 4 * j] = *(const float4*)(pe + 4 * j);
        }
    }
    __syncthreads();

    float tg = THITA_F * __ldg(gamma);
    int g = lane >> 2, tig = lane & 3;
    #pragma unroll
    for (int mt = 0; mt < 4; mt++) {
        int o = mt * 16 + g;
        float bb0 = __ldg(&bias[o]), bb1 = __ldg(&bias[o + 8]);
        #pragma unroll
        for (int nb = 0; nb < 4; nb++) {
            int pxl = wp * 32 + nb * 8 + tig * 2;
            int ndc = pxl >> 2;
            float a0 = tg * OS[o * 36 + ndc];
            float a1 = tg * OS[(o + 8) * 36 + ndc];
            float2 r0 = make_float2(fmaxf(acc[mt][nb][0] + bb0, 0.0f) + a0,
                                    fmaxf(acc[mt][nb][1] + bb0, 0.0f) + a0);
            float2 r1 = make_float2(fmaxf(acc[mt][nb][2] + bb1, 0.0f) + a1,
                                    fmaxf(acc[mt][nb][3] + bb1, 0.0f) + a1);
            *(float2*)(out + (size_t)(b * 64 + o)     * HW + p0 + pxl) = r0;
            *(float2*)(out + (size_t)(b * 64 + o + 8) * HW + p0 + pxl) = r1;
        }
    }

    int xq = t & 31, oo = t >> 5;
    #pragma unroll
    for (int rep = 0; rep < 16; rep++) {
        int o = rep * 4 + oo;
        float v = ES[o * 36 + xq];
        *(float4*)(out + OUT2OFF + (size_t)(b * 64 + o) * HW + p0 + (xq << 2)) =
            make_float4(v, v, v, v);
    }
}

// ============================================================================
extern "C" void kernel_launch(void* const* d_in, const int* in_sizes, int n_in,
                              void* d_out, int out_size)
{
    const float* x1    = (const float*)d_in[0];
    const float* x2    = (const float*)d_in[1];
    const float* ev    = (const float*)d_in[2];
    const float* xw0   = (const float*)d_in[3];
    const float* xb0   = (const float*)d_in[4];
    const float* xw1   = (const float*)d_in[5];
    const float* xb1   = (const float*)d_in[6];
    const float* ew0   = (const float*)d_in[7];
    const float* eb0   = (const float*)d_in[8];
    const float* ew1   = (const float*)d_in[9];
    const float* eb1   = (const float*)d_in[10];
    const float* qw    = (const float*)d_in[11];
    const float* qb    = (const float*)d_in[12];
    const float* kw    = (const float*)d_in[13];
    const float* kb    = (const float*)d_in[14];
    const float* vw    = (const float*)d_in[15];
    const float* vb    = (const float*)d_in[16];
    const float* gamma = (const float*)d_in[17];
    float* out = (float*)d_out;

    cudaFuncSetAttribute(prep_kernel,
                         cudaFuncAttributeMaxDynamicSharedMemorySize, PREP_SMEM);
    cudaFuncSetAttribute(qkv_kernel,
                         cudaFuncAttributeMaxDynamicSharedMemorySize, QKV_SMEM);
    cudaFuncSetAttribute(attn_kernel,
                         cudaFuncAttributeMaxDynamicSharedMemorySize, ATTN_SMEM);
    cudaFuncSetAttribute(convout_kernel,
                         cudaFuncAttributeMaxDynamicSharedMemorySize, CONVOUT_SMEM);

    wconv_kernel<<<48, 256>>>(xw0);
    prep_kernel<<<dim3(NDS / 64, BATCH, 2), 128, PREP_SMEM>>>(
        x1, x2, ev, xw0, xb0, ew0, eb0, ew1, eb1);
    qkv_kernel<<<dim3(NDS / 64, BATCH), 128, QKV_SMEM>>>(
        xw1, xb1, qw, qb, kw, kb, vw, vb);
    attn_kernel<<<dim3(NDS / 128, BATCH), 128, ATTN_SMEM>>>();

    {
        cudaLaunchConfig_t cfg = {};
        cfg.gridDim = dim3(512, BATCH, 1);
        cfg.blockDim = dim3(128, 1, 1);
        cfg.dynamicSmemBytes = CONVOUT_SMEM;
        cfg.stream = 0;
        cudaLaunchAttribute attrs[1];
        attrs[0].id = cudaLaunchAttributeProgrammaticStreamSerialization;
        attrs[0].val.programmaticStreamSerializationAllowed = 1;
        cfg.attrs = attrs;
        cfg.numAttrs = 1;
        cudaLaunchKernelEx(&cfg, convout_kernel, x1, x2, xb0, gamma, out);
    }
}